// round 13
// baseline (speedup 1.0000x reference)
#include <cuda_runtime.h>
#include <cuda_fp16.h>
#include <cuda_bf16.h>
#include <stdint.h>

#define NN 40000
#define EMAX 640000
#define DD 128
#define SCAN_BLK 256
#define PGRID 148                   // persistent GEMM CTAs (1/SM, 128KB smem)
#define THREADS_G 1024              // 32 warps/SM = max occupancy at 1 CTA/SM
#define TILES_MAX 625               // NN / 64 exactly

typedef unsigned long long ull;
typedef unsigned int u32;

// Scratch (allocation-free rule: __device__ globals)
__device__ __align__(16) __half g_z[NN * DD];       // z fp16: halves gather traffic
__device__ __align__(16) __nv_bfloat16 g_Ahi[TILES_MAX * 64 * DD];  // h split-bf16 tiles
__device__ __align__(16) __nv_bfloat16 g_Alo[TILES_MAX * 64 * DD];
__device__ int g_deg[NN];
__device__ int g_rowptr[NN + 1];
__device__ int g_ctr[NN];
__device__ int g_csrcol[EMAX];
__device__ int g_partial[1024];
__device__ int g_is64;
__device__ int g_tctr[4];                           // per-GEMM dynamic tile counters
__device__ __align__(16) __nv_bfloat16 g_Whi[3][16384];  // pre-swizzled W^T hi
__device__ __align__(16) __nv_bfloat16 g_Wlo[3][16384];  // pre-swizzled W^T lo

// ---------------------------------------------------------------------------
// Swizzled offset inside a [rows][128 cols] bf16 tile, pitch 256B.
// 16B chunk c of row r goes to chunk c ^ (r & 7) -> conflict-free ldmatrix.
// ---------------------------------------------------------------------------
__host__ __device__ __forceinline__ u32 tile_off(int r, int c16) {
    return (u32)r * 256u + (u32)((c16 ^ (r & 7)) << 4);
}

// ---------------------------------------------------------------------------
// mma.sync / ldmatrix / cp.async helpers (plain sm_103-legal)
// ---------------------------------------------------------------------------
__device__ __forceinline__ void mma16816(float* d, const u32* a, const u32* b) {
    asm volatile("mma.sync.aligned.m16n8k16.row.col.f32.bf16.bf16.f32 "
                 "{%0,%1,%2,%3}, {%4,%5,%6,%7}, {%8,%9}, {%0,%1,%2,%3};"
                 : "+f"(d[0]), "+f"(d[1]), "+f"(d[2]), "+f"(d[3])
                 : "r"(a[0]), "r"(a[1]), "r"(a[2]), "r"(a[3]),
                   "r"(b[0]), "r"(b[1]));
}
__device__ __forceinline__ void ldm_x4(u32* r, u32 addr) {
    asm volatile("ldmatrix.sync.aligned.m8n8.x4.shared.b16 {%0,%1,%2,%3}, [%4];"
                 : "=r"(r[0]), "=r"(r[1]), "=r"(r[2]), "=r"(r[3]) : "r"(addr));
}
__device__ __forceinline__ u32 smem_u32(const void* p) {
    u32 a;
    asm("{ .reg .u64 t; cvta.to.shared.u64 t, %1; cvt.u32.u64 %0, t; }" : "=r"(a) : "l"(p));
    return a;
}
#define CP_ASYNC16(d, s) asm volatile("cp.async.cg.shared.global [%0], [%1], 16;" :: "r"(d), "l"(s))
#define CP_COMMIT()      asm volatile("cp.async.commit_group;" ::: "memory")
#define CP_WAIT0()       asm volatile("cp.async.wait_group 0;" ::: "memory")

__device__ __forceinline__ void split_bf16(float v, unsigned short& h, unsigned short& lo) {
    __nv_bfloat16 hb = __float2bfloat16(v);
    h = __bfloat16_as_ushort(hb);
    lo = __bfloat16_as_ushort(__float2bfloat16(v - __bfloat162float(hb)));
}

// ---------------------------------------------------------------------------
__global__ void reset_ctr_kernel(int start) {
    if (threadIdx.x < 4) g_tctr[threadIdx.x] = start;
}

// ---------------------------------------------------------------------------
// W conversion: fp32 W [k][n] -> split-bf16 W^T tiles [n row][k col], swizzled.
// ---------------------------------------------------------------------------
__global__ void wconv_kernel(const float* __restrict__ W,
                             __nv_bfloat16* __restrict__ hi,
                             __nv_bfloat16* __restrict__ lo) {
    int idx = blockIdx.x * 256 + threadIdx.x;
    if (idx >= 16384) return;
    int k = idx >> 7, nn = idx & 127;
    unsigned short hs, ls;
    split_bf16(W[idx], hs, ls);
    u32 off = tile_off(nn, k >> 3) + (u32)(k & 7) * 2u;
    *(unsigned short*)((char*)hi + off) = hs;
    *(unsigned short*)((char*)lo + off) = ls;
}

// ---------------------------------------------------------------------------
// Pipelined persistent tensor-core GEMM: C[n,128] = A @ W (+bias).
// 64x128x128 tile; 1024 threads = 32 warps in 4(M) x 8(N); warp: 16M x 16N.
// LOAD_SPLIT=1: A from pre-split global tiles via cp.async (double-buffered).
// LOAD_SPLIT=0: A fp32 -> register prefetch -> convert at iteration end.
// SPLIT_OUT=1: epilogue also writes split-bf16 tiles of the output (fp32 path).
// Smem: W hi 32K | W lo 32K | buf0 (Ahi16K|Alo16K) | buf1 | queue slots.
// ---------------------------------------------------------------------------
#define GEMM_SMEM (131072 + 32)

template <int LOAD_SPLIT, int HALF_OUT, int SPLIT_OUT>
__global__ __launch_bounds__(THREADS_G, 1)
void tgemm_kernel(const float* __restrict__ Af32,
                  const __nv_bfloat16* __restrict__ Ahi_g,
                  const __nv_bfloat16* __restrict__ Alo_g,
                  const __nv_bfloat16* __restrict__ Whi,
                  const __nv_bfloat16* __restrict__ Wlo,
                  const float* __restrict__ bias, void* __restrict__ Cv,
                  __nv_bfloat16* __restrict__ Ohi, __nv_bfloat16* __restrict__ Olo,
                  int n, int ntiles, int slot) {
    extern __shared__ char smem[];
    const u32 sb = smem_u32(smem);
    int* nextp = (int*)(smem + 131072);

    const int tid = threadIdx.x;
    const int wid = tid >> 5;
    const int l   = tid & 31;
    const int R0  = (wid >> 3) * 16;     // 0,16,32,48
    const int N0  = (wid & 7) * 16;      // 0..112

    // ldmatrix lane address components
    const int ar = (l & 15);
    const int ac = (l >> 4);
    const int br = (l & 7) + ((l >> 4) & 1) * 8;
    const int bc = (l >> 3) & 1;

    // Prologue: W hi/lo via cp.async (2048 16B chunks each, 2/thread)
    #pragma unroll
    for (int i = 0; i < 2; ++i) {
        u32 d = sb + (u32)(tid + i * 1024) * 16u;
        CP_ASYNC16(d,         (const char*)Whi + (tid + i * 1024) * 16);
        CP_ASYNC16(d + 32768, (const char*)Wlo + (tid + i * 1024) * 16);
    }

    // Bias pairs per lane (fp32 out path)
    float2 bv[2];
    bv[0] = make_float2(0.f, 0.f); bv[1] = make_float2(0.f, 0.f);
    if (!HALF_OUT && bias) {
        bv[0] = *(const float2*)(bias + N0 + 0 + 2 * (l & 3));
        bv[1] = *(const float2*)(bias + N0 + 8 + 2 * (l & 3));
    }

    float4 pre[2];                       // convert-mode register prefetch

    int t_cur = blockIdx.x;

    // First A tile
    if (t_cur < ntiles) {
        if (LOAD_SPLIT) {
            u32 dst = sb + 65536;
            const char* shp = (const char*)Ahi_g + (size_t)t_cur * 16384;
            const char* slp = (const char*)Alo_g + (size_t)t_cur * 16384;
            CP_ASYNC16(dst + (u32)tid * 16u, shp + tid * 16);
            CP_ASYNC16(dst + 16384 + (u32)tid * 16u, slp + tid * 16);
        } else {
            #pragma unroll
            for (int i = 0; i < 2; ++i) {
                int e4 = tid + i * 1024;
                int row = t_cur * 64 + (e4 >> 5);
                pre[i] = make_float4(0.f, 0.f, 0.f, 0.f);
                if (row < n) pre[i] = *(const float4*)(Af32 + (size_t)row * DD + (e4 & 31) * 4);
            }
        }
    }
    CP_COMMIT();
    if (tid == 0) nextp[0] = atomicAdd(&g_tctr[slot], 1);
    CP_WAIT0();
    if (!LOAD_SPLIT && t_cur < ntiles) {
        char* dst = smem + 65536;
        #pragma unroll
        for (int i = 0; i < 2; ++i) {
            int e4 = tid + i * 1024;
            int r = e4 >> 5, c4 = e4 & 31;
            float f[4] = {pre[i].x, pre[i].y, pre[i].z, pre[i].w};
            unsigned short hs[4], ls[4];
            #pragma unroll
            for (int j = 0; j < 4; ++j) split_bf16(f[j], hs[j], ls[j]);
            u32 off = tile_off(r, c4 >> 1) + (u32)(c4 & 1) * 8u;
            *(ushort4*)(dst + off)         = make_ushort4(hs[0], hs[1], hs[2], hs[3]);
            *(ushort4*)(dst + 16384 + off) = make_ushort4(ls[0], ls[1], ls[2], ls[3]);
        }
    }
    __syncthreads();
    int parity = 0, cur = 0;
    int t_next = nextp[0];

    while (t_cur < ntiles) {
        // Kick off next tile load into buf[cur^1]
        if (t_next < ntiles) {
            if (LOAD_SPLIT) {
                u32 dst = sb + 65536 + (u32)(cur ^ 1) * 32768u;
                const char* shp = (const char*)Ahi_g + (size_t)t_next * 16384;
                const char* slp = (const char*)Alo_g + (size_t)t_next * 16384;
                CP_ASYNC16(dst + (u32)tid * 16u, shp + tid * 16);
                CP_ASYNC16(dst + 16384 + (u32)tid * 16u, slp + tid * 16);
                CP_COMMIT();
            } else {
                #pragma unroll
                for (int i = 0; i < 2; ++i) {
                    int e4 = tid + i * 1024;
                    int row = t_next * 64 + (e4 >> 5);
                    pre[i] = make_float4(0.f, 0.f, 0.f, 0.f);
                    if (row < n) pre[i] = *(const float4*)(Af32 + (size_t)row * DD + (e4 & 31) * 4);
                }
            }
        }
        if (tid == 0) nextp[parity ^ 1] = atomicAdd(&g_tctr[slot], 1);

        // ---- MMA on buf[cur] ----
        const u32 aAh = sb + 65536 + (u32)cur * 32768u;
        const u32 aAl = aAh + 16384;

        float acc[2][4];
        #pragma unroll
        for (int nb = 0; nb < 2; ++nb)
            #pragma unroll
            for (int q = 0; q < 4; ++q) acc[nb][q] = 0.f;

        #pragma unroll
        for (int kk = 0; kk < 8; ++kk) {
            u32 ah[4], al[4], bh[4], bl[4];
            u32 aoff = tile_off(R0 + ar, 2 * kk + ac);
            ldm_x4(ah, aAh + aoff);
            ldm_x4(al, aAl + aoff);
            u32 boff = tile_off(N0 + br, 2 * kk + bc);
            ldm_x4(bh, sb + boff);
            ldm_x4(bl, sb + 32768 + boff);
            mma16816(acc[0], ah, bh + 0);
            mma16816(acc[0], ah, bl + 0);
            mma16816(acc[0], al, bh + 0);
            mma16816(acc[1], ah, bh + 2);
            mma16816(acc[1], ah, bl + 2);
            mma16816(acc[1], al, bh + 2);
        }

        // Convert-mode: store prefetched next tile into buf[cur^1]
        if (!LOAD_SPLIT && t_next < ntiles) {
            char* dst = smem + 65536 + (cur ^ 1) * 32768;
            #pragma unroll
            for (int i = 0; i < 2; ++i) {
                int e4 = tid + i * 1024;
                int r = e4 >> 5, c4 = e4 & 31;
                float f[4] = {pre[i].x, pre[i].y, pre[i].z, pre[i].w};
                unsigned short hs[4], ls[4];
                #pragma unroll
                for (int j = 0; j < 4; ++j) split_bf16(f[j], hs[j], ls[j]);
                u32 off = tile_off(r, c4 >> 1) + (u32)(c4 & 1) * 8u;
                *(ushort4*)(dst + off)         = make_ushort4(hs[0], hs[1], hs[2], hs[3]);
                *(ushort4*)(dst + 16384 + off) = make_ushort4(ls[0], ls[1], ls[2], ls[3]);
            }
        }

        // ---- Epilogue for t_cur ----
        {
            int rows[2];
            rows[0] = t_cur * 64 + R0 + (l >> 2);
            rows[1] = rows[0] + 8;
            #pragma unroll
            for (int nb = 0; nb < 2; ++nb) {
                int col = N0 + nb * 8 + 2 * (l & 3);
                const float* d = acc[nb];
                #pragma unroll
                for (int h2 = 0; h2 < 2; ++h2) {
                    int row = rows[h2];
                    if (row >= n) continue;
                    float v0 = d[2 * h2 + 0], v1 = d[2 * h2 + 1];
                    if (HALF_OUT) {
                        *(__half2*)((__half*)Cv + (size_t)row * DD + col) =
                            __floats2half2_rn(v0, v1);
                    } else {
                        v0 += bv[nb].x; v1 += bv[nb].y;
                        *(float2*)((float*)Cv + (size_t)row * DD + col) = make_float2(v0, v1);
                        if (SPLIT_OUT) {
                            unsigned short h0, l0, h1, l1;
                            split_bf16(v0, h0, l0);
                            split_bf16(v1, h1, l1);
                            size_t o = (size_t)(row >> 6) * 16384 +
                                       tile_off(row & 63, col >> 3) + (col & 7) * 2;
                            *(u32*)((char*)Ohi + o) = (u32)h0 | ((u32)h1 << 16);
                            *(u32*)((char*)Olo + o) = (u32)l0 | ((u32)l1 << 16);
                        }
                    }
                }
            }
        }

        CP_WAIT0();
        __syncthreads();
        t_cur = t_next;
        t_next = nextp[parity ^ 1];
        parity ^= 1;
        cur ^= 1;
    }
}

// ---------------------------------------------------------------------------
// Detect int64 vs int32 edge_index: one warp, 128 values, ballot.
// ---------------------------------------------------------------------------
__global__ void detect_idx_kernel(const long long* __restrict__ p) {
    int t = threadIdx.x;
    int bad = 0;
    #pragma unroll
    for (int i = 0; i < 4; ++i) {
        long long v = p[t + i * 32];
        bad |= (v < 0 || v >= NN);
    }
    unsigned m = __ballot_sync(0xffffffffu, bad);
    if (t == 0) g_is64 = (m == 0);
}

__device__ __forceinline__ int load_idx(const void* p, int i) {
    return g_is64 ? (int)((const long long*)p)[i] : ((const int*)p)[i];
}

// ---------------------------------------------------------------------------
// CSR construction: zero -> histogram -> 3-phase scan -> fill
// ---------------------------------------------------------------------------
__global__ void zero_deg_kernel(int* __restrict__ deg, int n) {
    int i = blockIdx.x * blockDim.x + threadIdx.x;
    if (i < n) deg[i] = 0;
}

__global__ void hist_kernel(const void* __restrict__ eidx, int* __restrict__ deg, int E) {
    int e = blockIdx.x * blockDim.x + threadIdx.x;
    if (e >= E) return;
    atomicAdd(&deg[load_idx(eidx, e)], 1);
}

__global__ void scan_phase1(const int* __restrict__ deg, int* __restrict__ rowptr,
                            int* __restrict__ partial, int n) {
    __shared__ int sm[SCAN_BLK];
    const int t = threadIdx.x;
    const int i = blockIdx.x * SCAN_BLK + t;
    int v = (i < n) ? deg[i] : 0;
    sm[t] = v;
    __syncthreads();
    #pragma unroll
    for (int off = 1; off < SCAN_BLK; off <<= 1) {
        int u = (t >= off) ? sm[t - off] : 0;
        __syncthreads();
        sm[t] += u;
        __syncthreads();
    }
    if (i < n) rowptr[i] = sm[t] - v;
    if (t == SCAN_BLK - 1) partial[blockIdx.x] = sm[t];
}

__global__ void scan_phase2(int* __restrict__ partial, int nb,
                            int* __restrict__ rowptr, int n, int E) {
    __shared__ int sm[1024];
    const int t = threadIdx.x;
    int v = (t < nb) ? partial[t] : 0;
    sm[t] = v;
    __syncthreads();
    #pragma unroll
    for (int off = 1; off < 1024; off <<= 1) {
        int u = (t >= off) ? sm[t - off] : 0;
        __syncthreads();
        sm[t] += u;
        __syncthreads();
    }
    if (t < nb) partial[t] = sm[t] - v;
    if (t == 0) rowptr[n] = E;
}

__global__ void scan_phase3(int* __restrict__ rowptr, int* __restrict__ ctr,
                            const int* __restrict__ partial, int n) {
    int i = blockIdx.x * SCAN_BLK + threadIdx.x;
    if (i < n) {
        int v = rowptr[i] + partial[blockIdx.x];
        rowptr[i] = v;
        ctr[i] = v;
    }
}

__global__ void fill_kernel(const void* __restrict__ eidx, int* __restrict__ ctr,
                            int* __restrict__ csrcol, int E) {
    int e = blockIdx.x * blockDim.x + threadIdx.x;
    if (e >= E) return;
    int row = load_idx(eidx, e);
    int col = load_idx(eidx, E + e);
    int pos = atomicAdd(&ctr[row], 1);
    csrcol[pos] = col;
}

// ---------------------------------------------------------------------------
// Fused gather-aggregate + relu + residual: one warp per node, z in fp16.
// SPLIT_OUT=1 additionally writes the updated h as split-bf16 tiles.
// ---------------------------------------------------------------------------
template <int SPLIT_OUT>
__global__ __launch_bounds__(256)
void gather_relu_res_kernel(const int* __restrict__ rowptr,
                            const int* __restrict__ csrcol,
                            const __half* __restrict__ z,
                            float* __restrict__ h,
                            const float* __restrict__ b,
                            __nv_bfloat16* __restrict__ Ohi,
                            __nv_bfloat16* __restrict__ Olo, int n) {
    int warp = (blockIdx.x * blockDim.x + threadIdx.x) >> 5;
    int lane = threadIdx.x & 31;
    if (warp >= n) return;

    const int s = rowptr[warp];
    const int e = rowptr[warp + 1];
    const int off = lane * 4;

    float4 acc = make_float4(0.f, 0.f, 0.f, 0.f);

    int j = s;
    for (; j + 4 <= e; j += 4) {
        int c0 = csrcol[j + 0];
        int c1 = csrcol[j + 1];
        int c2 = csrcol[j + 2];
        int c3 = csrcol[j + 3];
        __half2 p0[2], p1[2], p2[2], p3[2];
        *reinterpret_cast<uint2*>(p0) = *reinterpret_cast<const uint2*>(z + (size_t)c0 * DD + off);
        *reinterpret_cast<uint2*>(p1) = *reinterpret_cast<const uint2*>(z + (size_t)c1 * DD + off);
        *reinterpret_cast<uint2*>(p2) = *reinterpret_cast<const uint2*>(z + (size_t)c2 * DD + off);
        *reinterpret_cast<uint2*>(p3) = *reinterpret_cast<const uint2*>(z + (size_t)c3 * DD + off);
        float2 f;
        f = __half22float2(p0[0]); acc.x += f.x; acc.y += f.y;
        f = __half22float2(p0[1]); acc.z += f.x; acc.w += f.y;
        f = __half22float2(p1[0]); acc.x += f.x; acc.y += f.y;
        f = __half22float2(p1[1]); acc.z += f.x; acc.w += f.y;
        f = __half22float2(p2[0]); acc.x += f.x; acc.y += f.y;
        f = __half22float2(p2[1]); acc.z += f.x; acc.w += f.y;
        f = __half22float2(p3[0]); acc.x += f.x; acc.y += f.y;
        f = __half22float2(p3[1]); acc.z += f.x; acc.w += f.y;
    }
    for (; j < e; ++j) {
        int c = csrcol[j];
        __half2 p[2];
        *reinterpret_cast<uint2*>(p) = *reinterpret_cast<const uint2*>(z + (size_t)c * DD + off);
        float2 f;
        f = __half22float2(p[0]); acc.x += f.x; acc.y += f.y;
        f = __half22float2(p[1]); acc.z += f.x; acc.w += f.y;
    }

    float4 bvv = *reinterpret_cast<const float4*>(b + off);
    float4 hv = *reinterpret_cast<float4*>(h + (size_t)warp * DD + off);
    hv.x += fmaxf(acc.x + bvv.x, 0.f);
    hv.y += fmaxf(acc.y + bvv.y, 0.f);
    hv.z += fmaxf(acc.z + bvv.z, 0.f);
    hv.w += fmaxf(acc.w + bvv.w, 0.f);
    *reinterpret_cast<float4*>(h + (size_t)warp * DD + off) = hv;

    if (SPLIT_OUT) {
        float v[4] = {hv.x, hv.y, hv.z, hv.w};
        unsigned short hs[4], ls[4];
        #pragma unroll
        for (int q = 0; q < 4; ++q) split_bf16(v[q], hs[q], ls[q]);
        size_t o = (size_t)(warp >> 6) * 16384 +
                   tile_off(warp & 63, off >> 3) + (off & 7) * 2;
        *(ushort4*)((char*)Ohi + o) = make_ushort4(hs[0], hs[1], hs[2], hs[3]);
        *(ushort4*)((char*)Olo + o) = make_ushort4(ls[0], ls[1], ls[2], ls[3]);
    }
}

// ---------------------------------------------------------------------------
extern "C" void kernel_launch(void* const* d_in, const int* in_sizes, int n_in,
                              void* d_out, int out_size) {
    const float* x   = (const float*)d_in[0];
    const void*  eix = d_in[1];
    const float* W_t = (const float*)d_in[2];
    const float* b_t = (const float*)d_in[3];
    const float* W0  = (const float*)d_in[4];
    const float* b0  = (const float*)d_in[5];
    const float* W1  = (const float*)d_in[6];
    const float* b1  = (const float*)d_in[7];
    float* h = (float*)d_out;

    const int n = in_sizes[0] / DD;   // 40000
    const int E = in_sizes[1] / 2;    // 640000

    __half* z_ptr;
    int *deg_ptr, *rowptr_ptr, *ctr_ptr, *csrcol_ptr, *partial_ptr;
    __nv_bfloat16 *whi, *wlo, *ahi, *alo;
    cudaGetSymbolAddress((void**)&z_ptr, g_z);
    cudaGetSymbolAddress((void**)&deg_ptr, g_deg);
    cudaGetSymbolAddress((void**)&rowptr_ptr, g_rowptr);
    cudaGetSymbolAddress((void**)&ctr_ptr, g_ctr);
    cudaGetSymbolAddress((void**)&csrcol_ptr, g_csrcol);
    cudaGetSymbolAddress((void**)&partial_ptr, g_partial);
    cudaGetSymbolAddress((void**)&whi, g_Whi);
    cudaGetSymbolAddress((void**)&wlo, g_Wlo);
    cudaGetSymbolAddress((void**)&ahi, g_Ahi);
    cudaGetSymbolAddress((void**)&alo, g_Alo);

    cudaFuncSetAttribute(tgemm_kernel<0, 0, 1>,
                         cudaFuncAttributeMaxDynamicSharedMemorySize, GEMM_SMEM);
    cudaFuncSetAttribute(tgemm_kernel<1, 1, 0>,
                         cudaFuncAttributeMaxDynamicSharedMemorySize, GEMM_SMEM);

    const int ntiles = (n + 63) / 64;               // 625
    const int ggrid  = ntiles < PGRID ? ntiles : PGRID;
    const int edge_blocks = (E + 255) / 256;
    const int node_blocks = (n * 32 + 255) / 256;   // warp per node
    const int scan_blocks = (n + SCAN_BLK - 1) / SCAN_BLK;

    // Side stream for W conversion + CSR build (host objects only; graph
    // replays execute the captured graph, not this host code).
    cudaStream_t side;
    cudaStreamCreateWithFlags(&side, cudaStreamNonBlocking);
    cudaEvent_t evF, evW, evJ;
    cudaEventCreateWithFlags(&evF, cudaEventDisableTiming);
    cudaEventCreateWithFlags(&evW, cudaEventDisableTiming);
    cudaEventCreateWithFlags(&evJ, cudaEventDisableTiming);

    cudaEventRecord(evF, 0);
    cudaStreamWaitEvent(side, evF, 0);

    // Launch-submission order keeps tgemm_t at index 3 (ncu window).
    reset_ctr_kernel<<<1, 32>>>(ggrid);                              // 0 main
    wconv_kernel<<<64, 256, 0, side>>>(W_t, whi, wlo);               // 1 side
    wconv_kernel<<<64, 256, 0, side>>>(W0, whi + 16384, wlo + 16384);// 2 side
    cudaEventRecord(evW, side);
    cudaStreamWaitEvent(0, evW, 0);
    // h = x @ W_t + b_t ; also emit h as split-bf16 tiles for GEMM_0
    tgemm_kernel<0, 0, 1><<<ggrid, THREADS_G, GEMM_SMEM>>>(
        x, nullptr, nullptr, whi, wlo, b_t, h, ahi, alo, n, ntiles, 0);  // 3 main
    wconv_kernel<<<64, 256, 0, side>>>(W1, whi + 2 * 16384, wlo + 2 * 16384);
    detect_idx_kernel<<<1, 32, 0, side>>>((const long long*)eix);
    zero_deg_kernel<<<(n + 255) / 256, 256, 0, side>>>(deg_ptr, n);
    hist_kernel<<<edge_blocks, 256, 0, side>>>(eix, deg_ptr, E);
    scan_phase1<<<scan_blocks, SCAN_BLK, 0, side>>>(deg_ptr, rowptr_ptr, partial_ptr, n);
    scan_phase2<<<1, 1024, 0, side>>>(partial_ptr, scan_blocks, rowptr_ptr, n, E);
    scan_phase3<<<scan_blocks, SCAN_BLK, 0, side>>>(rowptr_ptr, ctr_ptr, partial_ptr, n);
    fill_kernel<<<edge_blocks, 256, 0, side>>>(eix, ctr_ptr, csrcol_ptr, E);
    cudaEventRecord(evJ, side);

    // z = h @ W0 (fp16 out), A from split tiles
    tgemm_kernel<1, 1, 0><<<ggrid, THREADS_G, GEMM_SMEM>>>(
        nullptr, ahi, alo, whi + 16384, wlo + 16384, nullptr, z_ptr,
        nullptr, nullptr, n, ntiles, 1);

    // join: gathers need the CSR
    cudaStreamWaitEvent(0, evJ, 0);

    // layer 0: h += relu(gather(z) + b0); also refresh split-bf16 h tiles
    gather_relu_res_kernel<1><<<node_blocks, 256>>>(
        rowptr_ptr, csrcol_ptr, z_ptr, h, b0, ahi, alo, n);

    // layer 1
    tgemm_kernel<1, 1, 0><<<ggrid, THREADS_G, GEMM_SMEM>>>(
        nullptr, ahi, alo, whi + 2 * 16384, wlo + 2 * 16384, nullptr, z_ptr,
        nullptr, nullptr, n, ntiles, 2);
    gather_relu_res_kernel<0><<<node_blocks, 256>>>(
        rowptr_ptr, csrcol_ptr, z_ptr, h, b1, nullptr, nullptr, n);
}

// round 14
// speedup vs baseline: 1.0515x; 1.0515x over previous
#include <cuda_runtime.h>
#include <cuda_fp16.h>
#include <cuda_bf16.h>
#include <stdint.h>

#define NN 40000
#define EMAX 640000
#define DD 128
#define SCAN_BLK 256
#define PGRID 148                   // persistent GEMM CTAs (1/SM, 128KB smem)
#define THREADS_G 512
#define TILES_MAX 625               // NN / 64 exactly

typedef unsigned long long ull;
typedef unsigned int u32;

// Scratch (allocation-free rule: __device__ globals)
__device__ __align__(16) __half g_z[NN * DD];       // z fp16: halves gather traffic
__device__ __align__(16) __nv_bfloat16 g_Ahi[TILES_MAX * 64 * DD];  // h split-bf16 tiles
__device__ __align__(16) __nv_bfloat16 g_Alo[TILES_MAX * 64 * DD];
__device__ __align__(16) __nv_bfloat16 g_Xhi[TILES_MAX * 64 * DD];  // x split-bf16 tiles
__device__ __align__(16) __nv_bfloat16 g_Xlo[TILES_MAX * 64 * DD];
__device__ int g_deg[NN];
__device__ int g_rowptr[NN + 1];
__device__ int g_ctr[NN];
__device__ int g_csrcol[EMAX];
__device__ int g_partial[1024];
__device__ int g_is64;
__device__ int g_tctr[4];                           // per-GEMM dynamic tile counters
__device__ __align__(16) __nv_bfloat16 g_Whi[3][16384];  // pre-swizzled W^T hi
__device__ __align__(16) __nv_bfloat16 g_Wlo[3][16384];  // pre-swizzled W^T lo

// ---------------------------------------------------------------------------
// Swizzled offset inside a [rows][128 cols] bf16 tile, pitch 256B.
// 16B chunk c of row r goes to chunk c ^ (r & 7) -> conflict-free ldmatrix.
// ---------------------------------------------------------------------------
__host__ __device__ __forceinline__ u32 tile_off(int r, int c16) {
    return (u32)r * 256u + (u32)((c16 ^ (r & 7)) << 4);
}

// ---------------------------------------------------------------------------
// mma.sync / ldmatrix / cp.async helpers (plain sm_103-legal)
// ---------------------------------------------------------------------------
__device__ __forceinline__ void mma16816(float* d, const u32* a, const u32* b) {
    asm volatile("mma.sync.aligned.m16n8k16.row.col.f32.bf16.bf16.f32 "
                 "{%0,%1,%2,%3}, {%4,%5,%6,%7}, {%8,%9}, {%0,%1,%2,%3};"
                 : "+f"(d[0]), "+f"(d[1]), "+f"(d[2]), "+f"(d[3])
                 : "r"(a[0]), "r"(a[1]), "r"(a[2]), "r"(a[3]),
                   "r"(b[0]), "r"(b[1]));
}
__device__ __forceinline__ void ldm_x4(u32* r, u32 addr) {
    asm volatile("ldmatrix.sync.aligned.m8n8.x4.shared.b16 {%0,%1,%2,%3}, [%4];"
                 : "=r"(r[0]), "=r"(r[1]), "=r"(r[2]), "=r"(r[3]) : "r"(addr));
}
__device__ __forceinline__ u32 smem_u32(const void* p) {
    u32 a;
    asm("{ .reg .u64 t; cvta.to.shared.u64 t, %1; cvt.u32.u64 %0, t; }" : "=r"(a) : "l"(p));
    return a;
}
#define CP_ASYNC16(d, s) asm volatile("cp.async.cg.shared.global [%0], [%1], 16;" :: "r"(d), "l"(s))
#define CP_COMMIT()      asm volatile("cp.async.commit_group;" ::: "memory")
#define CP_WAIT0()       asm volatile("cp.async.wait_group 0;" ::: "memory")

__device__ __forceinline__ void split_bf16(float v, unsigned short& h, unsigned short& lo) {
    __nv_bfloat16 hb = __float2bfloat16(v);
    h = __bfloat16_as_ushort(hb);
    lo = __bfloat16_as_ushort(__float2bfloat16(v - __bfloat162float(hb)));
}

// ---------------------------------------------------------------------------
__global__ void reset_ctr_kernel(int start) {
    if (threadIdx.x < 4) g_tctr[threadIdx.x] = start;
}

// ---------------------------------------------------------------------------
// x conversion: fp32 [n,128] -> split-bf16 swizzled 64-row tiles.
// One float4 per thread; streaming, ~40MB total traffic.
// ---------------------------------------------------------------------------
__global__ void xsplit_kernel(const float* __restrict__ X,
                              __nv_bfloat16* __restrict__ hi,
                              __nv_bfloat16* __restrict__ lo, int n) {
    int e4 = blockIdx.x * blockDim.x + threadIdx.x;
    if (e4 >= n * 32) return;
    int row = e4 >> 5;
    int c4 = e4 & 31;
    float4 v = *(const float4*)(X + (size_t)row * DD + c4 * 4);
    float f[4] = {v.x, v.y, v.z, v.w};
    unsigned short hs[4], ls[4];
    #pragma unroll
    for (int j = 0; j < 4; ++j) split_bf16(f[j], hs[j], ls[j]);
    size_t o = (size_t)(row >> 6) * 16384 + tile_off(row & 63, c4 >> 1) + (c4 & 1) * 8;
    *(ushort4*)((char*)hi + o) = make_ushort4(hs[0], hs[1], hs[2], hs[3]);
    *(ushort4*)((char*)lo + o) = make_ushort4(ls[0], ls[1], ls[2], ls[3]);
}

// ---------------------------------------------------------------------------
// W conversion: fp32 W [k][n] -> split-bf16 W^T tiles [n row][k col], swizzled.
// ---------------------------------------------------------------------------
__global__ void wconv_kernel(const float* __restrict__ W,
                             __nv_bfloat16* __restrict__ hi,
                             __nv_bfloat16* __restrict__ lo) {
    int idx = blockIdx.x * 256 + threadIdx.x;
    if (idx >= 16384) return;
    int k = idx >> 7, nn = idx & 127;
    unsigned short hs, ls;
    split_bf16(W[idx], hs, ls);
    u32 off = tile_off(nn, k >> 3) + (u32)(k & 7) * 2u;
    *(unsigned short*)((char*)hi + off) = hs;
    *(unsigned short*)((char*)lo + off) = ls;
}

// ---------------------------------------------------------------------------
// Pipelined persistent tensor-core GEMM: C[n,128] = A @ W (+bias).
// 64x128x128 tile; 512 threads = 16 warps in 2(M) x 8(N); warp: 32M x 16N.
// A always from pre-split global tiles via cp.async (double-buffered).
// SPLIT_OUT=1: epilogue also writes split-bf16 tiles of the output (fp32 path).
// Smem: W hi 32K | W lo 32K | buf0 (Ahi16K|Alo16K) | buf1 | queue slots.
// ---------------------------------------------------------------------------
#define GEMM_SMEM (131072 + 32)

template <int HALF_OUT, int SPLIT_OUT>
__global__ __launch_bounds__(THREADS_G, 1)
void tgemm_kernel(const __nv_bfloat16* __restrict__ Ahi_g,
                  const __nv_bfloat16* __restrict__ Alo_g,
                  const __nv_bfloat16* __restrict__ Whi,
                  const __nv_bfloat16* __restrict__ Wlo,
                  const float* __restrict__ bias, void* __restrict__ Cv,
                  __nv_bfloat16* __restrict__ Ohi, __nv_bfloat16* __restrict__ Olo,
                  int n, int ntiles, int slot) {
    extern __shared__ char smem[];
    const u32 sb = smem_u32(smem);
    int* nextp = (int*)(smem + 131072);

    const int tid = threadIdx.x;
    const int wid = tid >> 5;
    const int l   = tid & 31;
    const int R0  = (wid >> 3) * 32;     // 0 or 32
    const int N0  = (wid & 7) * 16;      // 0..112

    // ldmatrix lane address components
    const int ar = (l & 15);
    const int ac = (l >> 4);
    const int br = (l & 7) + ((l >> 4) & 1) * 8;
    const int bc = (l >> 3) & 1;

    // Prologue: W hi/lo via cp.async (2048 16B chunks each, 4/thread)
    #pragma unroll
    for (int i = 0; i < 4; ++i) {
        u32 d = sb + (u32)(tid + i * 512) * 16u;
        CP_ASYNC16(d,         (const char*)Whi + (tid + i * 512) * 16);
        CP_ASYNC16(d + 32768, (const char*)Wlo + (tid + i * 512) * 16);
    }

    // Bias pairs per lane (fp32 out path)
    float2 bv[2];
    bv[0] = make_float2(0.f, 0.f); bv[1] = make_float2(0.f, 0.f);
    if (!HALF_OUT && bias) {
        bv[0] = *(const float2*)(bias + N0 + 0 + 2 * (l & 3));
        bv[1] = *(const float2*)(bias + N0 + 8 + 2 * (l & 3));
    }

    int t_cur = blockIdx.x;

    // First A tile
    if (t_cur < ntiles) {
        u32 dst = sb + 65536;
        const char* shp = (const char*)Ahi_g + (size_t)t_cur * 16384;
        const char* slp = (const char*)Alo_g + (size_t)t_cur * 16384;
        #pragma unroll
        for (int i = 0; i < 2; ++i) {
            CP_ASYNC16(dst + (u32)(tid + i * 512) * 16u, shp + (tid + i * 512) * 16);
            CP_ASYNC16(dst + 16384 + (u32)(tid + i * 512) * 16u, slp + (tid + i * 512) * 16);
        }
    }
    CP_COMMIT();
    if (tid == 0) nextp[0] = atomicAdd(&g_tctr[slot], 1);
    CP_WAIT0();
    __syncthreads();
    int parity = 0, cur = 0;
    int t_next = nextp[0];

    while (t_cur < ntiles) {
        // Kick off next tile load into buf[cur^1]
        if (t_next < ntiles) {
            u32 dst = sb + 65536 + (u32)(cur ^ 1) * 32768u;
            const char* shp = (const char*)Ahi_g + (size_t)t_next * 16384;
            const char* slp = (const char*)Alo_g + (size_t)t_next * 16384;
            #pragma unroll
            for (int i = 0; i < 2; ++i) {
                CP_ASYNC16(dst + (u32)(tid + i * 512) * 16u, shp + (tid + i * 512) * 16);
                CP_ASYNC16(dst + 16384 + (u32)(tid + i * 512) * 16u, slp + (tid + i * 512) * 16);
            }
            CP_COMMIT();
        }
        if (tid == 0) nextp[parity ^ 1] = atomicAdd(&g_tctr[slot], 1);

        // ---- MMA on buf[cur] ----
        const u32 aAh = sb + 65536 + (u32)cur * 32768u;
        const u32 aAl = aAh + 16384;

        float acc[2][2][4];
        #pragma unroll
        for (int mt = 0; mt < 2; ++mt)
            #pragma unroll
            for (int nb = 0; nb < 2; ++nb)
                #pragma unroll
                for (int q = 0; q < 4; ++q) acc[mt][nb][q] = 0.f;

        #pragma unroll
        for (int kk = 0; kk < 8; ++kk) {
            u32 ah[2][4], al[2][4], bh[4], bl[4];
            #pragma unroll
            for (int mt = 0; mt < 2; ++mt) {
                u32 off = tile_off(R0 + mt * 16 + ar, 2 * kk + ac);
                ldm_x4(ah[mt], aAh + off);
                ldm_x4(al[mt], aAl + off);
            }
            u32 boff = tile_off(N0 + br, 2 * kk + bc);
            ldm_x4(bh, sb + boff);
            ldm_x4(bl, sb + 32768 + boff);
            #pragma unroll
            for (int mt = 0; mt < 2; ++mt) {
                mma16816(acc[mt][0], ah[mt], bh + 0);
                mma16816(acc[mt][0], ah[mt], bl + 0);
                mma16816(acc[mt][0], al[mt], bh + 0);
                mma16816(acc[mt][1], ah[mt], bh + 2);
                mma16816(acc[mt][1], ah[mt], bl + 2);
                mma16816(acc[mt][1], al[mt], bh + 2);
            }
        }

        // ---- Epilogue for t_cur ----
        #pragma unroll
        for (int mt = 0; mt < 2; ++mt) {
            int rows[2];
            rows[0] = t_cur * 64 + R0 + mt * 16 + (l >> 2);
            rows[1] = rows[0] + 8;
            #pragma unroll
            for (int nb = 0; nb < 2; ++nb) {
                int col = N0 + nb * 8 + 2 * (l & 3);
                const float* d = acc[mt][nb];
                #pragma unroll
                for (int h2 = 0; h2 < 2; ++h2) {
                    int row = rows[h2];
                    if (row >= n) continue;
                    float v0 = d[2 * h2 + 0], v1 = d[2 * h2 + 1];
                    if (HALF_OUT) {
                        *(__half2*)((__half*)Cv + (size_t)row * DD + col) =
                            __floats2half2_rn(v0, v1);
                    } else {
                        v0 += bv[nb].x; v1 += bv[nb].y;
                        *(float2*)((float*)Cv + (size_t)row * DD + col) = make_float2(v0, v1);
                        if (SPLIT_OUT) {
                            unsigned short h0, l0, h1, l1;
                            split_bf16(v0, h0, l0);
                            split_bf16(v1, h1, l1);
                            size_t o = (size_t)(row >> 6) * 16384 +
                                       tile_off(row & 63, col >> 3) + (col & 7) * 2;
                            *(u32*)((char*)Ohi + o) = (u32)h0 | ((u32)h1 << 16);
                            *(u32*)((char*)Olo + o) = (u32)l0 | ((u32)l1 << 16);
                        }
                    }
                }
            }
        }

        CP_WAIT0();
        __syncthreads();
        t_cur = t_next;
        t_next = nextp[parity ^ 1];
        parity ^= 1;
        cur ^= 1;
    }
}

// ---------------------------------------------------------------------------
// Detect int64 vs int32 edge_index: one warp, 128 values, ballot.
// ---------------------------------------------------------------------------
__global__ void detect_idx_kernel(const long long* __restrict__ p) {
    int t = threadIdx.x;
    int bad = 0;
    #pragma unroll
    for (int i = 0; i < 4; ++i) {
        long long v = p[t + i * 32];
        bad |= (v < 0 || v >= NN);
    }
    unsigned m = __ballot_sync(0xffffffffu, bad);
    if (t == 0) g_is64 = (m == 0);
}

__device__ __forceinline__ int load_idx(const void* p, int i) {
    return g_is64 ? (int)((const long long*)p)[i] : ((const int*)p)[i];
}

// ---------------------------------------------------------------------------
// CSR construction: zero -> histogram -> 3-phase scan -> fill
// ---------------------------------------------------------------------------
__global__ void zero_deg_kernel(int* __restrict__ deg, int n) {
    int i = blockIdx.x * blockDim.x + threadIdx.x;
    if (i < n) deg[i] = 0;
}

__global__ void hist_kernel(const void* __restrict__ eidx, int* __restrict__ deg, int E) {
    int e = blockIdx.x * blockDim.x + threadIdx.x;
    if (e >= E) return;
    atomicAdd(&deg[load_idx(eidx, e)], 1);
}

__global__ void scan_phase1(const int* __restrict__ deg, int* __restrict__ rowptr,
                            int* __restrict__ partial, int n) {
    __shared__ int sm[SCAN_BLK];
    const int t = threadIdx.x;
    const int i = blockIdx.x * SCAN_BLK + t;
    int v = (i < n) ? deg[i] : 0;
    sm[t] = v;
    __syncthreads();
    #pragma unroll
    for (int off = 1; off < SCAN_BLK; off <<= 1) {
        int u = (t >= off) ? sm[t - off] : 0;
        __syncthreads();
        sm[t] += u;
        __syncthreads();
    }
    if (i < n) rowptr[i] = sm[t] - v;
    if (t == SCAN_BLK - 1) partial[blockIdx.x] = sm[t];
}

__global__ void scan_phase2(int* __restrict__ partial, int nb,
                            int* __restrict__ rowptr, int n, int E) {
    __shared__ int sm[1024];
    const int t = threadIdx.x;
    int v = (t < nb) ? partial[t] : 0;
    sm[t] = v;
    __syncthreads();
    #pragma unroll
    for (int off = 1; off < 1024; off <<= 1) {
        int u = (t >= off) ? sm[t - off] : 0;
        __syncthreads();
        sm[t] += u;
        __syncthreads();
    }
    if (t < nb) partial[t] = sm[t] - v;
    if (t == 0) rowptr[n] = E;
}

__global__ void scan_phase3(int* __restrict__ rowptr, int* __restrict__ ctr,
                            const int* __restrict__ partial, int n) {
    int i = blockIdx.x * SCAN_BLK + threadIdx.x;
    if (i < n) {
        int v = rowptr[i] + partial[blockIdx.x];
        rowptr[i] = v;
        ctr[i] = v;
    }
}

__global__ void fill_kernel(const void* __restrict__ eidx, int* __restrict__ ctr,
                            int* __restrict__ csrcol, int E) {
    int e = blockIdx.x * blockDim.x + threadIdx.x;
    if (e >= E) return;
    int row = load_idx(eidx, e);
    int col = load_idx(eidx, E + e);
    int pos = atomicAdd(&ctr[row], 1);
    csrcol[pos] = col;
}

// ---------------------------------------------------------------------------
// Fused gather-aggregate + relu + residual: one warp per node, z in fp16.
// SPLIT_OUT=1 additionally writes the updated h as split-bf16 tiles.
// ---------------------------------------------------------------------------
template <int SPLIT_OUT>
__global__ __launch_bounds__(256)
void gather_relu_res_kernel(const int* __restrict__ rowptr,
                            const int* __restrict__ csrcol,
                            const __half* __restrict__ z,
                            float* __restrict__ h,
                            const float* __restrict__ b,
                            __nv_bfloat16* __restrict__ Ohi,
                            __nv_bfloat16* __restrict__ Olo, int n) {
    int warp = (blockIdx.x * blockDim.x + threadIdx.x) >> 5;
    int lane = threadIdx.x & 31;
    if (warp >= n) return;

    const int s = rowptr[warp];
    const int e = rowptr[warp + 1];
    const int off = lane * 4;

    float4 acc = make_float4(0.f, 0.f, 0.f, 0.f);

    int j = s;
    for (; j + 4 <= e; j += 4) {
        int c0 = csrcol[j + 0];
        int c1 = csrcol[j + 1];
        int c2 = csrcol[j + 2];
        int c3 = csrcol[j + 3];
        __half2 p0[2], p1[2], p2[2], p3[2];
        *reinterpret_cast<uint2*>(p0) = *reinterpret_cast<const uint2*>(z + (size_t)c0 * DD + off);
        *reinterpret_cast<uint2*>(p1) = *reinterpret_cast<const uint2*>(z + (size_t)c1 * DD + off);
        *reinterpret_cast<uint2*>(p2) = *reinterpret_cast<const uint2*>(z + (size_t)c2 * DD + off);
        *reinterpret_cast<uint2*>(p3) = *reinterpret_cast<const uint2*>(z + (size_t)c3 * DD + off);
        float2 f;
        f = __half22float2(p0[0]); acc.x += f.x; acc.y += f.y;
        f = __half22float2(p0[1]); acc.z += f.x; acc.w += f.y;
        f = __half22float2(p1[0]); acc.x += f.x; acc.y += f.y;
        f = __half22float2(p1[1]); acc.z += f.x; acc.w += f.y;
        f = __half22float2(p2[0]); acc.x += f.x; acc.y += f.y;
        f = __half22float2(p2[1]); acc.z += f.x; acc.w += f.y;
        f = __half22float2(p3[0]); acc.x += f.x; acc.y += f.y;
        f = __half22float2(p3[1]); acc.z += f.x; acc.w += f.y;
    }
    for (; j < e; ++j) {
        int c = csrcol[j];
        __half2 p[2];
        *reinterpret_cast<uint2*>(p) = *reinterpret_cast<const uint2*>(z + (size_t)c * DD + off);
        float2 f;
        f = __half22float2(p[0]); acc.x += f.x; acc.y += f.y;
        f = __half22float2(p[1]); acc.z += f.x; acc.w += f.y;
    }

    float4 bvv = *reinterpret_cast<const float4*>(b + off);
    float4 hv = *reinterpret_cast<float4*>(h + (size_t)warp * DD + off);
    hv.x += fmaxf(acc.x + bvv.x, 0.f);
    hv.y += fmaxf(acc.y + bvv.y, 0.f);
    hv.z += fmaxf(acc.z + bvv.z, 0.f);
    hv.w += fmaxf(acc.w + bvv.w, 0.f);
    *reinterpret_cast<float4*>(h + (size_t)warp * DD + off) = hv;

    if (SPLIT_OUT) {
        float v[4] = {hv.x, hv.y, hv.z, hv.w};
        unsigned short hs[4], ls[4];
        #pragma unroll
        for (int q = 0; q < 4; ++q) split_bf16(v[q], hs[q], ls[q]);
        size_t o = (size_t)(warp >> 6) * 16384 +
                   tile_off(warp & 63, off >> 3) + (off & 7) * 2;
        *(ushort4*)((char*)Ohi + o) = make_ushort4(hs[0], hs[1], hs[2], hs[3]);
        *(ushort4*)((char*)Olo + o) = make_ushort4(ls[0], ls[1], ls[2], ls[3]);
    }
}

// ---------------------------------------------------------------------------
extern "C" void kernel_launch(void* const* d_in, const int* in_sizes, int n_in,
                              void* d_out, int out_size) {
    const float* x   = (const float*)d_in[0];
    const void*  eix = d_in[1];
    const float* W_t = (const float*)d_in[2];
    const float* b_t = (const float*)d_in[3];
    const float* W0  = (const float*)d_in[4];
    const float* b0  = (const float*)d_in[5];
    const float* W1  = (const float*)d_in[6];
    const float* b1  = (const float*)d_in[7];
    float* h = (float*)d_out;

    const int n = in_sizes[0] / DD;   // 40000
    const int E = in_sizes[1] / 2;    // 640000

    __half* z_ptr;
    int *deg_ptr, *rowptr_ptr, *ctr_ptr, *csrcol_ptr, *partial_ptr;
    __nv_bfloat16 *whi, *wlo, *ahi, *alo, *xhi, *xlo;
    cudaGetSymbolAddress((void**)&z_ptr, g_z);
    cudaGetSymbolAddress((void**)&deg_ptr, g_deg);
    cudaGetSymbolAddress((void**)&rowptr_ptr, g_rowptr);
    cudaGetSymbolAddress((void**)&ctr_ptr, g_ctr);
    cudaGetSymbolAddress((void**)&csrcol_ptr, g_csrcol);
    cudaGetSymbolAddress((void**)&partial_ptr, g_partial);
    cudaGetSymbolAddress((void**)&whi, g_Whi);
    cudaGetSymbolAddress((void**)&wlo, g_Wlo);
    cudaGetSymbolAddress((void**)&ahi, g_Ahi);
    cudaGetSymbolAddress((void**)&alo, g_Alo);
    cudaGetSymbolAddress((void**)&xhi, g_Xhi);
    cudaGetSymbolAddress((void**)&xlo, g_Xlo);

    cudaFuncSetAttribute(tgemm_kernel<0, 1>,
                         cudaFuncAttributeMaxDynamicSharedMemorySize, GEMM_SMEM);
    cudaFuncSetAttribute(tgemm_kernel<1, 0>,
                         cudaFuncAttributeMaxDynamicSharedMemorySize, GEMM_SMEM);

    const int ntiles = (n + 63) / 64;               // 625
    const int ggrid  = ntiles < PGRID ? ntiles : PGRID;
    const int edge_blocks = (E + 255) / 256;
    const int node_blocks = (n * 32 + 255) / 256;   // warp per node
    const int scan_blocks = (n + SCAN_BLK - 1) / SCAN_BLK;

    // Side stream for W conversion + CSR build (host objects only; graph
    // replays execute the captured graph, not this host code).
    cudaStream_t side;
    cudaStreamCreateWithFlags(&side, cudaStreamNonBlocking);
    cudaEvent_t evF, evW, evJ;
    cudaEventCreateWithFlags(&evF, cudaEventDisableTiming);
    cudaEventCreateWithFlags(&evW, cudaEventDisableTiming);
    cudaEventCreateWithFlags(&evJ, cudaEventDisableTiming);

    cudaEventRecord(evF, 0);
    cudaStreamWaitEvent(side, evF, 0);

    reset_ctr_kernel<<<1, 32>>>(ggrid);                              // main
    xsplit_kernel<<<(n * 32 + 255) / 256, 256>>>(x, xhi, xlo, n);    // main (critical)
    wconv_kernel<<<64, 256, 0, side>>>(W_t, whi, wlo);               // side
    wconv_kernel<<<64, 256, 0, side>>>(W0, whi + 16384, wlo + 16384);// side
    cudaEventRecord(evW, side);
    cudaStreamWaitEvent(0, evW, 0);
    // h = x @ W_t + b_t ; also emit h as split-bf16 tiles for GEMM_0
    tgemm_kernel<0, 1><<<ggrid, THREADS_G, GEMM_SMEM>>>(
        xhi, xlo, whi, wlo, b_t, h, ahi, alo, n, ntiles, 0);
    wconv_kernel<<<64, 256, 0, side>>>(W1, whi + 2 * 16384, wlo + 2 * 16384);
    detect_idx_kernel<<<1, 32, 0, side>>>((const long long*)eix);
    zero_deg_kernel<<<(n + 255) / 256, 256, 0, side>>>(deg_ptr, n);
    hist_kernel<<<edge_blocks, 256, 0, side>>>(eix, deg_ptr, E);
    scan_phase1<<<scan_blocks, SCAN_BLK, 0, side>>>(deg_ptr, rowptr_ptr, partial_ptr, n);
    scan_phase2<<<1, 1024, 0, side>>>(partial_ptr, scan_blocks, rowptr_ptr, n, E);
    scan_phase3<<<scan_blocks, SCAN_BLK, 0, side>>>(rowptr_ptr, ctr_ptr, partial_ptr, n);
    fill_kernel<<<edge_blocks, 256, 0, side>>>(eix, ctr_ptr, csrcol_ptr, E);
    cudaEventRecord(evJ, side);

    // z = h @ W0 (fp16 out), A from split tiles
    tgemm_kernel<1, 0><<<ggrid, THREADS_G, GEMM_SMEM>>>(
        ahi, alo, whi + 16384, wlo + 16384, nullptr, z_ptr,
        nullptr, nullptr, n, ntiles, 1);

    // join: gathers need the CSR
    cudaStreamWaitEvent(0, evJ, 0);

    // layer 0: h += relu(gather(z) + b0); also refresh split-bf16 h tiles
    gather_relu_res_kernel<1><<<node_blocks, 256>>>(
        rowptr_ptr, csrcol_ptr, z_ptr, h, b0, ahi, alo, n);

    // layer 1
    tgemm_kernel<1, 0><<<ggrid, THREADS_G, GEMM_SMEM>>>(
        ahi, alo, whi + 2 * 16384, wlo + 2 * 16384, nullptr, z_ptr,
        nullptr, nullptr, n, ntiles, 2);
    gather_relu_res_kernel<0><<<node_blocks, 256>>>(
        rowptr_ptr, csrcol_ptr, z_ptr, h, b1, nullptr, nullptr, n);
}

// round 15
// speedup vs baseline: 1.0685x; 1.0162x over previous
#include <cuda_runtime.h>
#include <cuda_fp16.h>
#include <cuda_bf16.h>
#include <stdint.h>

#define NN 40000
#define EMAX 640000
#define DD 128
#define SCAN_BLK 256
#define PGRID 148                   // persistent GEMM CTAs (1/SM, 128KB smem)
#define THREADS_G 512
#define TILES_MAX 625               // NN / 64 exactly

typedef unsigned long long ull;
typedef unsigned int u32;

// Scratch (allocation-free rule: __device__ globals)
__device__ __align__(16) __half g_z[NN * DD];       // z fp16: halves gather traffic
__device__ __align__(16) __nv_bfloat16 g_Ahi[TILES_MAX * 64 * DD];  // h split-bf16 tiles
__device__ __align__(16) __nv_bfloat16 g_Alo[TILES_MAX * 64 * DD];
__device__ int g_deg[NN];
__device__ int g_rowptr[NN + 1];
__device__ int g_ctr[NN];
__device__ int g_csrcol[EMAX];
__device__ int g_partial[1024];
__device__ int g_is64;
__device__ int g_tctr[4];                           // per-GEMM dynamic tile counters
__device__ __align__(16) __nv_bfloat16 g_Whi[2][16384];  // pre-swizzled W0/W1 hi
__device__ __align__(16) __nv_bfloat16 g_Wlo[2][16384];  // pre-swizzled W0/W1 lo

// ---------------------------------------------------------------------------
// Swizzled offset inside a [rows][128 cols] bf16 tile, pitch 256B.
// 16B chunk c of row r goes to chunk c ^ (r & 7) -> conflict-free ldmatrix.
// ---------------------------------------------------------------------------
__host__ __device__ __forceinline__ u32 tile_off(int r, int c16) {
    return (u32)r * 256u + (u32)((c16 ^ (r & 7)) << 4);
}

// ---------------------------------------------------------------------------
// mma.sync / ldmatrix / cp.async helpers (plain sm_103-legal)
// ---------------------------------------------------------------------------
__device__ __forceinline__ void mma16816(float* d, const u32* a, const u32* b) {
    asm volatile("mma.sync.aligned.m16n8k16.row.col.f32.bf16.bf16.f32 "
                 "{%0,%1,%2,%3}, {%4,%5,%6,%7}, {%8,%9}, {%0,%1,%2,%3};"
                 : "+f"(d[0]), "+f"(d[1]), "+f"(d[2]), "+f"(d[3])
                 : "r"(a[0]), "r"(a[1]), "r"(a[2]), "r"(a[3]),
                   "r"(b[0]), "r"(b[1]));
}
__device__ __forceinline__ void ldm_x4(u32* r, u32 addr) {
    asm volatile("ldmatrix.sync.aligned.m8n8.x4.shared.b16 {%0,%1,%2,%3}, [%4];"
                 : "=r"(r[0]), "=r"(r[1]), "=r"(r[2]), "=r"(r[3]) : "r"(addr));
}
__device__ __forceinline__ u32 smem_u32(const void* p) {
    u32 a;
    asm("{ .reg .u64 t; cvta.to.shared.u64 t, %1; cvt.u32.u64 %0, t; }" : "=r"(a) : "l"(p));
    return a;
}
#define CP_ASYNC16(d, s) asm volatile("cp.async.cg.shared.global [%0], [%1], 16;" :: "r"(d), "l"(s))
#define CP_COMMIT()      asm volatile("cp.async.commit_group;" ::: "memory")
#define CP_WAIT0()       asm volatile("cp.async.wait_group 0;" ::: "memory")

__device__ __forceinline__ void split_bf16(float v, unsigned short& h, unsigned short& lo) {
    __nv_bfloat16 hb = __float2bfloat16(v);
    h = __bfloat16_as_ushort(hb);
    lo = __bfloat16_as_ushort(__float2bfloat16(v - __bfloat162float(hb)));
}

// ---------------------------------------------------------------------------
__global__ void reset_ctr_kernel(int start) {
    if (threadIdx.x < 4) g_tctr[threadIdx.x] = start;
}

// ---------------------------------------------------------------------------
// W conversion: fp32 W [k][n] -> split-bf16 W^T tiles [n row][k col], swizzled.
// (Used for W0/W1 only; GEMM_t converts W_t in-kernel.)
// ---------------------------------------------------------------------------
__global__ void wconv_kernel(const float* __restrict__ W,
                             __nv_bfloat16* __restrict__ hi,
                             __nv_bfloat16* __restrict__ lo) {
    int idx = blockIdx.x * 256 + threadIdx.x;
    if (idx >= 16384) return;
    int k = idx >> 7, nn = idx & 127;
    unsigned short hs, ls;
    split_bf16(W[idx], hs, ls);
    u32 off = tile_off(nn, k >> 3) + (u32)(k & 7) * 2u;
    *(unsigned short*)((char*)hi + off) = hs;
    *(unsigned short*)((char*)lo + off) = ls;
}

// ---------------------------------------------------------------------------
// Pipelined persistent tensor-core GEMM: C[n,128] = A @ W (+bias).
// 64x128x128 tile; 512 threads = 16 warps in 2(M) x 8(N); warp: 32M x 16N.
// LOAD_SPLIT=1: A from pre-split global tiles via cp.async (double-buffered).
// LOAD_SPLIT=0: A fp32 -> register prefetch -> convert at iteration end.
// CONV_W=1: convert fp32 W in the prologue (no pre-swizzled W needed).
// SPLIT_OUT=1: epilogue also writes split-bf16 tiles of the output (fp32 path).
// Smem: W hi 32K | W lo 32K | buf0 (Ahi16K|Alo16K) | buf1 | queue slots.
// ---------------------------------------------------------------------------
#define GEMM_SMEM (131072 + 32)

template <int LOAD_SPLIT, int HALF_OUT, int SPLIT_OUT, int CONV_W>
__global__ __launch_bounds__(THREADS_G, 1)
void tgemm_kernel(const float* __restrict__ Af32,
                  const __nv_bfloat16* __restrict__ Ahi_g,
                  const __nv_bfloat16* __restrict__ Alo_g,
                  const __nv_bfloat16* __restrict__ Whi,
                  const __nv_bfloat16* __restrict__ Wlo,
                  const float* __restrict__ Wf32,
                  const float* __restrict__ bias, void* __restrict__ Cv,
                  __nv_bfloat16* __restrict__ Ohi, __nv_bfloat16* __restrict__ Olo,
                  int n, int ntiles, int slot) {
    extern __shared__ char smem[];
    const u32 sb = smem_u32(smem);
    int* nextp = (int*)(smem + 131072);

    const int tid = threadIdx.x;
    const int wid = tid >> 5;
    const int l   = tid & 31;
    const int R0  = (wid >> 3) * 32;     // 0 or 32
    const int N0  = (wid & 7) * 16;      // 0..112

    // ldmatrix lane address components
    const int ar = (l & 15);
    const int ac = (l >> 4);
    const int br = (l & 7) + ((l >> 4) & 1) * 8;
    const int bc = (l >> 3) & 1;

    // Prologue: W hi/lo
    if (CONV_W) {
        // Convert fp32 W [k][n] directly into swizzled smem.
        // Thread-fixed k (=tid&127), nn sweeps -> STS ~2-way conflicts only.
        const int k = tid & 127;
        const int nb = tid >> 7;          // 0..3
        const u32 kpart = tile_off(0, k >> 3) + (u32)(k & 7) * 2u;
        #pragma unroll
        for (int i = 0; i < 32; ++i) {
            int nn = nb + i * 4;
            unsigned short hs, ls;
            split_bf16(Wf32[k * 128 + nn], hs, ls);
            u32 off = (u32)nn * 256u + (kpart ^ (((u32)(nn & 7)) << 4));
            *(unsigned short*)(smem + off) = hs;
            *(unsigned short*)(smem + 32768 + off) = ls;
        }
    } else {
        #pragma unroll
        for (int i = 0; i < 4; ++i) {
            u32 d = sb + (u32)(tid + i * 512) * 16u;
            CP_ASYNC16(d,         (const char*)Whi + (tid + i * 512) * 16);
            CP_ASYNC16(d + 32768, (const char*)Wlo + (tid + i * 512) * 16);
        }
    }

    // Bias pairs per lane (fp32 out path)
    float2 bv[2];
    bv[0] = make_float2(0.f, 0.f); bv[1] = make_float2(0.f, 0.f);
    if (!HALF_OUT && bias) {
        bv[0] = *(const float2*)(bias + N0 + 0 + 2 * (l & 3));
        bv[1] = *(const float2*)(bias + N0 + 8 + 2 * (l & 3));
    }

    float4 pre[2];                       // convert-mode register prefetch

    int t_cur = blockIdx.x;

    // First A tile
    if (t_cur < ntiles) {
        if (LOAD_SPLIT) {
            u32 dst = sb + 65536;
            const char* shp = (const char*)Ahi_g + (size_t)t_cur * 16384;
            const char* slp = (const char*)Alo_g + (size_t)t_cur * 16384;
            #pragma unroll
            for (int i = 0; i < 2; ++i) {
                CP_ASYNC16(dst + (u32)(tid + i * 512) * 16u, shp + (tid + i * 512) * 16);
                CP_ASYNC16(dst + 16384 + (u32)(tid + i * 512) * 16u, slp + (tid + i * 512) * 16);
            }
        } else {
            #pragma unroll
            for (int i = 0; i < 2; ++i) {
                int e4 = tid + i * 512;
                int row = t_cur * 64 + (e4 >> 5);
                pre[i] = make_float4(0.f, 0.f, 0.f, 0.f);
                if (row < n) pre[i] = *(const float4*)(Af32 + (size_t)row * DD + (e4 & 31) * 4);
            }
            // second half (threads cover 2048 float4 per tile with 512 threads x4)
            // handled below via the same loop shape as R12:
        }
    }
    CP_COMMIT();
    if (tid == 0) nextp[0] = atomicAdd(&g_tctr[slot], 1);
    CP_WAIT0();
    if (!LOAD_SPLIT && t_cur < ntiles) {
        // convert prefetched half + load/convert remaining half into buf0
        char* dst = smem + 65536;
        #pragma unroll
        for (int i = 0; i < 2; ++i) {
            int e4 = tid + i * 512;
            int r = e4 >> 5, c4 = e4 & 31;
            float f[4] = {pre[i].x, pre[i].y, pre[i].z, pre[i].w};
            unsigned short hs[4], ls[4];
            #pragma unroll
            for (int j = 0; j < 4; ++j) split_bf16(f[j], hs[j], ls[j]);
            u32 off = tile_off(r, c4 >> 1) + (u32)(c4 & 1) * 8u;
            *(ushort4*)(dst + off)         = make_ushort4(hs[0], hs[1], hs[2], hs[3]);
            *(ushort4*)(dst + 16384 + off) = make_ushort4(ls[0], ls[1], ls[2], ls[3]);
        }
        #pragma unroll
        for (int i = 2; i < 4; ++i) {
            int e4 = tid + i * 512;
            int r = e4 >> 5, c4 = e4 & 31;
            int row = t_cur * 64 + r;
            float4 v = make_float4(0.f, 0.f, 0.f, 0.f);
            if (row < n) v = *(const float4*)(Af32 + (size_t)row * DD + c4 * 4);
            float f[4] = {v.x, v.y, v.z, v.w};
            unsigned short hs[4], ls[4];
            #pragma unroll
            for (int j = 0; j < 4; ++j) split_bf16(f[j], hs[j], ls[j]);
            u32 off = tile_off(r, c4 >> 1) + (u32)(c4 & 1) * 8u;
            *(ushort4*)(dst + off)         = make_ushort4(hs[0], hs[1], hs[2], hs[3]);
            *(ushort4*)(dst + 16384 + off) = make_ushort4(ls[0], ls[1], ls[2], ls[3]);
        }
    }
    __syncthreads();
    int parity = 0, cur = 0;
    int t_next = nextp[0];

    while (t_cur < ntiles) {
        // Kick off next tile load into buf[cur^1]
        if (t_next < ntiles) {
            if (LOAD_SPLIT) {
                u32 dst = sb + 65536 + (u32)(cur ^ 1) * 32768u;
                const char* shp = (const char*)Ahi_g + (size_t)t_next * 16384;
                const char* slp = (const char*)Alo_g + (size_t)t_next * 16384;
                #pragma unroll
                for (int i = 0; i < 2; ++i) {
                    CP_ASYNC16(dst + (u32)(tid + i * 512) * 16u, shp + (tid + i * 512) * 16);
                    CP_ASYNC16(dst + 16384 + (u32)(tid + i * 512) * 16u, slp + (tid + i * 512) * 16);
                }
                CP_COMMIT();
            } else {
                #pragma unroll
                for (int i = 0; i < 2; ++i) {
                    int e4 = tid + i * 512;
                    int row = t_next * 64 + (e4 >> 5);
                    pre[i] = make_float4(0.f, 0.f, 0.f, 0.f);
                    if (row < n) pre[i] = *(const float4*)(Af32 + (size_t)row * DD + (e4 & 31) * 4);
                }
            }
        }
        if (tid == 0) nextp[parity ^ 1] = atomicAdd(&g_tctr[slot], 1);

        // ---- MMA on buf[cur] ----
        const u32 aAh = sb + 65536 + (u32)cur * 32768u;
        const u32 aAl = aAh + 16384;

        float acc[2][2][4];
        #pragma unroll
        for (int mt = 0; mt < 2; ++mt)
            #pragma unroll
            for (int nb2 = 0; nb2 < 2; ++nb2)
                #pragma unroll
                for (int q = 0; q < 4; ++q) acc[mt][nb2][q] = 0.f;

        #pragma unroll
        for (int kk = 0; kk < 8; ++kk) {
            u32 ah[2][4], al[2][4], bh[4], bl[4];
            #pragma unroll
            for (int mt = 0; mt < 2; ++mt) {
                u32 off = tile_off(R0 + mt * 16 + ar, 2 * kk + ac);
                ldm_x4(ah[mt], aAh + off);
                ldm_x4(al[mt], aAl + off);
            }
            u32 boff = tile_off(N0 + br, 2 * kk + bc);
            ldm_x4(bh, sb + boff);
            ldm_x4(bl, sb + 32768 + boff);
            #pragma unroll
            for (int mt = 0; mt < 2; ++mt) {
                mma16816(acc[mt][0], ah[mt], bh + 0);
                mma16816(acc[mt][0], ah[mt], bl + 0);
                mma16816(acc[mt][0], al[mt], bh + 0);
                mma16816(acc[mt][1], ah[mt], bh + 2);
                mma16816(acc[mt][1], ah[mt], bl + 2);
                mma16816(acc[mt][1], al[mt], bh + 2);
            }
        }

        // Convert-mode: store prefetched half + load/convert rest into buf[cur^1]
        if (!LOAD_SPLIT && t_next < ntiles) {
            char* dst = smem + 65536 + (cur ^ 1) * 32768;
            #pragma unroll
            for (int i = 0; i < 2; ++i) {
                int e4 = tid + i * 512;
                int r = e4 >> 5, c4 = e4 & 31;
                float f[4] = {pre[i].x, pre[i].y, pre[i].z, pre[i].w};
                unsigned short hs[4], ls[4];
                #pragma unroll
                for (int j = 0; j < 4; ++j) split_bf16(f[j], hs[j], ls[j]);
                u32 off = tile_off(r, c4 >> 1) + (u32)(c4 & 1) * 8u;
                *(ushort4*)(dst + off)         = make_ushort4(hs[0], hs[1], hs[2], hs[3]);
                *(ushort4*)(dst + 16384 + off) = make_ushort4(ls[0], ls[1], ls[2], ls[3]);
            }
            #pragma unroll
            for (int i = 2; i < 4; ++i) {
                int e4 = tid + i * 512;
                int r = e4 >> 5, c4 = e4 & 31;
                int row = t_next * 64 + r;
                float4 v = make_float4(0.f, 0.f, 0.f, 0.f);
                if (row < n) v = *(const float4*)(Af32 + (size_t)row * DD + c4 * 4);
                float f[4] = {v.x, v.y, v.z, v.w};
                unsigned short hs[4], ls[4];
                #pragma unroll
                for (int j = 0; j < 4; ++j) split_bf16(f[j], hs[j], ls[j]);
                u32 off = tile_off(r, c4 >> 1) + (u32)(c4 & 1) * 8u;
                *(ushort4*)(dst + off)         = make_ushort4(hs[0], hs[1], hs[2], hs[3]);
                *(ushort4*)(dst + 16384 + off) = make_ushort4(ls[0], ls[1], ls[2], ls[3]);
            }
        }

        // ---- Epilogue for t_cur ----
        #pragma unroll
        for (int mt = 0; mt < 2; ++mt) {
            int rows[2];
            rows[0] = t_cur * 64 + R0 + mt * 16 + (l >> 2);
            rows[1] = rows[0] + 8;
            #pragma unroll
            for (int nb2 = 0; nb2 < 2; ++nb2) {
                int col = N0 + nb2 * 8 + 2 * (l & 3);
                const float* d = acc[mt][nb2];
                #pragma unroll
                for (int h2 = 0; h2 < 2; ++h2) {
                    int row = rows[h2];
                    if (row >= n) continue;
                    float v0 = d[2 * h2 + 0], v1 = d[2 * h2 + 1];
                    if (HALF_OUT) {
                        *(__half2*)((__half*)Cv + (size_t)row * DD + col) =
                            __floats2half2_rn(v0, v1);
                    } else {
                        v0 += bv[nb2].x; v1 += bv[nb2].y;
                        *(float2*)((float*)Cv + (size_t)row * DD + col) = make_float2(v0, v1);
                        if (SPLIT_OUT) {
                            unsigned short h0, l0, h1, l1;
                            split_bf16(v0, h0, l0);
                            split_bf16(v1, h1, l1);
                            size_t o = (size_t)(row >> 6) * 16384 +
                                       tile_off(row & 63, col >> 3) + (col & 7) * 2;
                            *(u32*)((char*)Ohi + o) = (u32)h0 | ((u32)h1 << 16);
                            *(u32*)((char*)Olo + o) = (u32)l0 | ((u32)l1 << 16);
                        }
                    }
                }
            }
        }

        CP_WAIT0();
        __syncthreads();
        t_cur = t_next;
        t_next = nextp[parity ^ 1];
        parity ^= 1;
        cur ^= 1;
    }
}

// ---------------------------------------------------------------------------
// Detect int64 vs int32 edge_index: one warp, 128 values, ballot.
// ---------------------------------------------------------------------------
__global__ void detect_idx_kernel(const long long* __restrict__ p) {
    int t = threadIdx.x;
    int bad = 0;
    #pragma unroll
    for (int i = 0; i < 4; ++i) {
        long long v = p[t + i * 32];
        bad |= (v < 0 || v >= NN);
    }
    unsigned m = __ballot_sync(0xffffffffu, bad);
    if (t == 0) g_is64 = (m == 0);
}

__device__ __forceinline__ int load_idx(const void* p, int i) {
    return g_is64 ? (int)((const long long*)p)[i] : ((const int*)p)[i];
}

// ---------------------------------------------------------------------------
// CSR construction: zero -> histogram -> 3-phase scan -> fill
// ---------------------------------------------------------------------------
__global__ void zero_deg_kernel(int* __restrict__ deg, int n) {
    int i = blockIdx.x * blockDim.x + threadIdx.x;
    if (i < n) deg[i] = 0;
}

__global__ void hist_kernel(const void* __restrict__ eidx, int* __restrict__ deg, int E) {
    int e = blockIdx.x * blockDim.x + threadIdx.x;
    if (e >= E) return;
    atomicAdd(&deg[load_idx(eidx, e)], 1);
}

__global__ void scan_phase1(const int* __restrict__ deg, int* __restrict__ rowptr,
                            int* __restrict__ partial, int n) {
    __shared__ int sm[SCAN_BLK];
    const int t = threadIdx.x;
    const int i = blockIdx.x * SCAN_BLK + t;
    int v = (i < n) ? deg[i] : 0;
    sm[t] = v;
    __syncthreads();
    #pragma unroll
    for (int off = 1; off < SCAN_BLK; off <<= 1) {
        int u = (t >= off) ? sm[t - off] : 0;
        __syncthreads();
        sm[t] += u;
        __syncthreads();
    }
    if (i < n) rowptr[i] = sm[t] - v;
    if (t == SCAN_BLK - 1) partial[blockIdx.x] = sm[t];
}

__global__ void scan_phase2(int* __restrict__ partial, int nb,
                            int* __restrict__ rowptr, int n, int E) {
    __shared__ int sm[1024];
    const int t = threadIdx.x;
    int v = (t < nb) ? partial[t] : 0;
    sm[t] = v;
    __syncthreads();
    #pragma unroll
    for (int off = 1; off < 1024; off <<= 1) {
        int u = (t >= off) ? sm[t - off] : 0;
        __syncthreads();
        sm[t] += u;
        __syncthreads();
    }
    if (t < nb) partial[t] = sm[t] - v;
    if (t == 0) rowptr[n] = E;
}

__global__ void scan_phase3(int* __restrict__ rowptr, int* __restrict__ ctr,
                            const int* __restrict__ partial, int n) {
    int i = blockIdx.x * SCAN_BLK + threadIdx.x;
    if (i < n) {
        int v = rowptr[i] + partial[blockIdx.x];
        rowptr[i] = v;
        ctr[i] = v;
    }
}

__global__ void fill_kernel(const void* __restrict__ eidx, int* __restrict__ ctr,
                            int* __restrict__ csrcol, int E) {
    int e = blockIdx.x * blockDim.x + threadIdx.x;
    if (e >= E) return;
    int row = load_idx(eidx, e);
    int col = load_idx(eidx, E + e);
    int pos = atomicAdd(&ctr[row], 1);
    csrcol[pos] = col;
}

// ---------------------------------------------------------------------------
// Fused gather-aggregate + relu + residual: one warp per node, z in fp16.
// SPLIT_OUT=1 additionally writes the updated h as split-bf16 tiles.
// ---------------------------------------------------------------------------
template <int SPLIT_OUT>
__global__ __launch_bounds__(256)
void gather_relu_res_kernel(const int* __restrict__ rowptr,
                            const int* __restrict__ csrcol,
                            const __half* __restrict__ z,
                            float* __restrict__ h,
                            const float* __restrict__ b,
                            __nv_bfloat16* __restrict__ Ohi,
                            __nv_bfloat16* __restrict__ Olo, int n) {
    int warp = (blockIdx.x * blockDim.x + threadIdx.x) >> 5;
    int lane = threadIdx.x & 31;
    if (warp >= n) return;

    const int s = rowptr[warp];
    const int e = rowptr[warp + 1];
    const int off = lane * 4;

    float4 acc = make_float4(0.f, 0.f, 0.f, 0.f);

    int j = s;
    for (; j + 4 <= e; j += 4) {
        int c0 = csrcol[j + 0];
        int c1 = csrcol[j + 1];
        int c2 = csrcol[j + 2];
        int c3 = csrcol[j + 3];
        __half2 p0[2], p1[2], p2[2], p3[2];
        *reinterpret_cast<uint2*>(p0) = *reinterpret_cast<const uint2*>(z + (size_t)c0 * DD + off);
        *reinterpret_cast<uint2*>(p1) = *reinterpret_cast<const uint2*>(z + (size_t)c1 * DD + off);
        *reinterpret_cast<uint2*>(p2) = *reinterpret_cast<const uint2*>(z + (size_t)c2 * DD + off);
        *reinterpret_cast<uint2*>(p3) = *reinterpret_cast<const uint2*>(z + (size_t)c3 * DD + off);
        float2 f;
        f = __half22float2(p0[0]); acc.x += f.x; acc.y += f.y;
        f = __half22float2(p0[1]); acc.z += f.x; acc.w += f.y;
        f = __half22float2(p1[0]); acc.x += f.x; acc.y += f.y;
        f = __half22float2(p1[1]); acc.z += f.x; acc.w += f.y;
        f = __half22float2(p2[0]); acc.x += f.x; acc.y += f.y;
        f = __half22float2(p2[1]); acc.z += f.x; acc.w += f.y;
        f = __half22float2(p3[0]); acc.x += f.x; acc.y += f.y;
        f = __half22float2(p3[1]); acc.z += f.x; acc.w += f.y;
    }
    for (; j < e; ++j) {
        int c = csrcol[j];
        __half2 p[2];
        *reinterpret_cast<uint2*>(p) = *reinterpret_cast<const uint2*>(z + (size_t)c * DD + off);
        float2 f;
        f = __half22float2(p[0]); acc.x += f.x; acc.y += f.y;
        f = __half22float2(p[1]); acc.z += f.x; acc.w += f.y;
    }

    float4 bvv = *reinterpret_cast<const float4*>(b + off);
    float4 hv = *reinterpret_cast<float4*>(h + (size_t)warp * DD + off);
    hv.x += fmaxf(acc.x + bvv.x, 0.f);
    hv.y += fmaxf(acc.y + bvv.y, 0.f);
    hv.z += fmaxf(acc.z + bvv.z, 0.f);
    hv.w += fmaxf(acc.w + bvv.w, 0.f);
    *reinterpret_cast<float4*>(h + (size_t)warp * DD + off) = hv;

    if (SPLIT_OUT) {
        float v[4] = {hv.x, hv.y, hv.z, hv.w};
        unsigned short hs[4], ls[4];
        #pragma unroll
        for (int q = 0; q < 4; ++q) split_bf16(v[q], hs[q], ls[q]);
        size_t o = (size_t)(warp >> 6) * 16384 +
                   tile_off(warp & 63, off >> 3) + (off & 7) * 2;
        *(ushort4*)((char*)Ohi + o) = make_ushort4(hs[0], hs[1], hs[2], hs[3]);
        *(ushort4*)((char*)Olo + o) = make_ushort4(ls[0], ls[1], ls[2], ls[3]);
    }
}

// ---------------------------------------------------------------------------
extern "C" void kernel_launch(void* const* d_in, const int* in_sizes, int n_in,
                              void* d_out, int out_size) {
    const float* x   = (const float*)d_in[0];
    const void*  eix = d_in[1];
    const float* W_t = (const float*)d_in[2];
    const float* b_t = (const float*)d_in[3];
    const float* W0  = (const float*)d_in[4];
    const float* b0  = (const float*)d_in[5];
    const float* W1  = (const float*)d_in[6];
    const float* b1  = (const float*)d_in[7];
    float* h = (float*)d_out;

    const int n = in_sizes[0] / DD;   // 40000
    const int E = in_sizes[1] / 2;    // 640000

    __half* z_ptr;
    int *deg_ptr, *rowptr_ptr, *ctr_ptr, *csrcol_ptr, *partial_ptr;
    __nv_bfloat16 *whi, *wlo, *ahi, *alo;
    cudaGetSymbolAddress((void**)&z_ptr, g_z);
    cudaGetSymbolAddress((void**)&deg_ptr, g_deg);
    cudaGetSymbolAddress((void**)&rowptr_ptr, g_rowptr);
    cudaGetSymbolAddress((void**)&ctr_ptr, g_ctr);
    cudaGetSymbolAddress((void**)&csrcol_ptr, g_csrcol);
    cudaGetSymbolAddress((void**)&partial_ptr, g_partial);
    cudaGetSymbolAddress((void**)&whi, g_Whi);
    cudaGetSymbolAddress((void**)&wlo, g_Wlo);
    cudaGetSymbolAddress((void**)&ahi, g_Ahi);
    cudaGetSymbolAddress((void**)&alo, g_Alo);

    cudaFuncSetAttribute(tgemm_kernel<0, 0, 1, 1>,
                         cudaFuncAttributeMaxDynamicSharedMemorySize, GEMM_SMEM);
    cudaFuncSetAttribute(tgemm_kernel<1, 1, 0, 0>,
                         cudaFuncAttributeMaxDynamicSharedMemorySize, GEMM_SMEM);

    const int ntiles = (n + 63) / 64;               // 625
    const int ggrid  = ntiles < PGRID ? ntiles : PGRID;
    const int edge_blocks = (E + 255) / 256;
    const int node_blocks = (n * 32 + 255) / 256;   // warp per node
    const int scan_blocks = (n + SCAN_BLK - 1) / SCAN_BLK;

    // Side stream (host objects only; replays execute the captured graph).
    cudaStream_t side;
    cudaStreamCreateWithFlags(&side, cudaStreamNonBlocking);
    cudaEvent_t evF, evW, evJ;
    cudaEventCreateWithFlags(&evF, cudaEventDisableTiming);
    cudaEventCreateWithFlags(&evW, cudaEventDisableTiming);
    cudaEventCreateWithFlags(&evJ, cudaEventDisableTiming);

    cudaEventRecord(evF, 0);
    cudaStreamWaitEvent(side, evF, 0);

    // Main starts GEMM_t immediately (in-kernel W_t conversion, no evW dep).
    reset_ctr_kernel<<<1, 32>>>(ggrid);                              // 0 main
    wconv_kernel<<<64, 256, 0, side>>>(W0, whi, wlo);                // 1 side
    wconv_kernel<<<64, 256, 0, side>>>(W1, whi + 16384, wlo + 16384);// 2 side
    tgemm_kernel<0, 0, 1, 1><<<ggrid, THREADS_G, GEMM_SMEM>>>(
        x, nullptr, nullptr, nullptr, nullptr, W_t, b_t, h,
        ahi, alo, n, ntiles, 0);                                     // 3 main (ncu)
    cudaEventRecord(evW, side);

    detect_idx_kernel<<<1, 32, 0, side>>>((const long long*)eix);
    zero_deg_kernel<<<(n + 255) / 256, 256, 0, side>>>(deg_ptr, n);
    hist_kernel<<<edge_blocks, 256, 0, side>>>(eix, deg_ptr, E);
    scan_phase1<<<scan_blocks, SCAN_BLK, 0, side>>>(deg_ptr, rowptr_ptr, partial_ptr, n);
    scan_phase2<<<1, 1024, 0, side>>>(partial_ptr, scan_blocks, rowptr_ptr, n, E);
    scan_phase3<<<scan_blocks, SCAN_BLK, 0, side>>>(rowptr_ptr, ctr_ptr, partial_ptr, n);
    fill_kernel<<<edge_blocks, 256, 0, side>>>(eix, ctr_ptr, csrcol_ptr, E);
    cudaEventRecord(evJ, side);

    // z = h @ W0 (fp16 out), A from split tiles; W0 conversion done by now
    cudaStreamWaitEvent(0, evW, 0);
    tgemm_kernel<1, 1, 0, 0><<<ggrid, THREADS_G, GEMM_SMEM>>>(
        nullptr, ahi, alo, whi, wlo, nullptr, nullptr, z_ptr,
        nullptr, nullptr, n, ntiles, 1);

    // join: gathers need the CSR
    cudaStreamWaitEvent(0, evJ, 0);

    // layer 0: h += relu(gather(z) + b0); also refresh split-bf16 h tiles
    gather_relu_res_kernel<1><<<node_blocks, 256>>>(
        rowptr_ptr, csrcol_ptr, z_ptr, h, b0, ahi, alo, n);

    // layer 1
    tgemm_kernel<1, 1, 0, 0><<<ggrid, THREADS_G, GEMM_SMEM>>>(
        nullptr, ahi, alo, whi + 16384, wlo + 16384, nullptr, nullptr, z_ptr,
        nullptr, nullptr, n, ntiles, 2);
    gather_relu_res_kernel<0><<<node_blocks, 256>>>(
        rowptr_ptr, csrcol_ptr, z_ptr, h, b1, nullptr, nullptr, n);
}

// round 16
// speedup vs baseline: 1.1406x; 1.0674x over previous
#include <cuda_runtime.h>
#include <cuda_fp16.h>
#include <cuda_bf16.h>
#include <stdint.h>

#define NN 40000
#define EMAX 640000
#define DD 128
#define SCAN_BLK 256
#define PGRID 148                   // persistent GEMM CTAs (1/SM, 128KB smem)
#define THREADS_G 512
#define TILES_MAX 625               // NN / 64 exactly

typedef unsigned long long ull;
typedef unsigned int u32;

// Scratch (allocation-free rule: __device__ globals)
__device__ __align__(16) __half g_z[NN * DD];       // z fp16: halves gather traffic
__device__ __align__(16) __nv_bfloat16 g_Ahi[TILES_MAX * 64 * DD];  // h split-bf16 tiles
__device__ __align__(16) __nv_bfloat16 g_Alo[TILES_MAX * 64 * DD];
__device__ int g_deg[NN];
__device__ int g_rowptr[NN + 1];
__device__ int g_ctr[NN];
__device__ int g_csrcol[EMAX];
__device__ int g_partial[1024];
__device__ int g_is64;
__device__ int g_tctr[4];                           // per-GEMM dynamic tile counters
__device__ __align__(16) __nv_bfloat16 g_Whi[3][16384];  // pre-swizzled W^T hi
__device__ __align__(16) __nv_bfloat16 g_Wlo[3][16384];  // pre-swizzled W^T lo

// ---------------------------------------------------------------------------
// Swizzled offset inside a [rows][128 cols] bf16 tile, pitch 256B.
// 16B chunk c of row r goes to chunk c ^ (r & 7) -> conflict-free ldmatrix.
// ---------------------------------------------------------------------------
__host__ __device__ __forceinline__ u32 tile_off(int r, int c16) {
    return (u32)r * 256u + (u32)((c16 ^ (r & 7)) << 4);
}

// ---------------------------------------------------------------------------
// mma.sync / ldmatrix / cp.async helpers (plain sm_103-legal)
// ---------------------------------------------------------------------------
__device__ __forceinline__ void mma16816(float* d, const u32* a, const u32* b) {
    asm volatile("mma.sync.aligned.m16n8k16.row.col.f32.bf16.bf16.f32 "
                 "{%0,%1,%2,%3}, {%4,%5,%6,%7}, {%8,%9}, {%0,%1,%2,%3};"
                 : "+f"(d[0]), "+f"(d[1]), "+f"(d[2]), "+f"(d[3])
                 : "r"(a[0]), "r"(a[1]), "r"(a[2]), "r"(a[3]),
                   "r"(b[0]), "r"(b[1]));
}
__device__ __forceinline__ void ldm_x4(u32* r, u32 addr) {
    asm volatile("ldmatrix.sync.aligned.m8n8.x4.shared.b16 {%0,%1,%2,%3}, [%4];"
                 : "=r"(r[0]), "=r"(r[1]), "=r"(r[2]), "=r"(r[3]) : "r"(addr));
}
__device__ __forceinline__ u32 smem_u32(const void* p) {
    u32 a;
    asm("{ .reg .u64 t; cvta.to.shared.u64 t, %1; cvt.u32.u64 %0, t; }" : "=r"(a) : "l"(p));
    return a;
}
#define CP_ASYNC16(d, s) asm volatile("cp.async.cg.shared.global [%0], [%1], 16;" :: "r"(d), "l"(s))
#define CP_COMMIT()      asm volatile("cp.async.commit_group;" ::: "memory")
#define CP_WAIT0()       asm volatile("cp.async.wait_group 0;" ::: "memory")

__device__ __forceinline__ void split_bf16(float v, unsigned short& h, unsigned short& lo) {
    __nv_bfloat16 hb = __float2bfloat16(v);
    h = __bfloat16_as_ushort(hb);
    lo = __bfloat16_as_ushort(__float2bfloat16(v - __bfloat162float(hb)));
}

// ---------------------------------------------------------------------------
// W conversion: fp32 W [k][n] -> split-bf16 W^T tiles [n row][k col], swizzled.
// DO_RESET: block 0 also resets the dynamic tile counters (main-stream use).
// ---------------------------------------------------------------------------
__global__ void wconv_kernel(const float* __restrict__ W,
                             __nv_bfloat16* __restrict__ hi,
                             __nv_bfloat16* __restrict__ lo,
                             int do_reset, int start) {
    if (do_reset && blockIdx.x == 0 && threadIdx.x < 4) g_tctr[threadIdx.x] = start;
    int idx = blockIdx.x * 256 + threadIdx.x;
    if (idx >= 16384) return;
    int k = idx >> 7, nn = idx & 127;
    unsigned short hs, ls;
    split_bf16(W[idx], hs, ls);
    u32 off = tile_off(nn, k >> 3) + (u32)(k & 7) * 2u;
    *(unsigned short*)((char*)hi + off) = hs;
    *(unsigned short*)((char*)lo + off) = ls;
}

// ---------------------------------------------------------------------------
// Pipelined persistent tensor-core GEMM: C[n,128] = A @ W (+bias).
// 64x128x128 tile; 512 threads = 16 warps in 2(M) x 8(N); warp: 32M x 16N.
// LOAD_SPLIT=1: A from pre-split global tiles via cp.async (double-buffered).
// LOAD_SPLIT=0: A fp32 -> register prefetch -> convert at iteration end.
// SPLIT_OUT=1: epilogue also writes split-bf16 tiles of the output (fp32 path).
// Smem: W hi 32K | W lo 32K | buf0 (Ahi16K|Alo16K) | buf1 | queue slots.
// ---------------------------------------------------------------------------
#define GEMM_SMEM (131072 + 32)

template <int LOAD_SPLIT, int HALF_OUT, int SPLIT_OUT>
__global__ __launch_bounds__(THREADS_G, 1)
void tgemm_kernel(const float* __restrict__ Af32,
                  const __nv_bfloat16* __restrict__ Ahi_g,
                  const __nv_bfloat16* __restrict__ Alo_g,
                  const __nv_bfloat16* __restrict__ Whi,
                  const __nv_bfloat16* __restrict__ Wlo,
                  const float* __restrict__ bias, void* __restrict__ Cv,
                  __nv_bfloat16* __restrict__ Ohi, __nv_bfloat16* __restrict__ Olo,
                  int n, int ntiles, int slot) {
    extern __shared__ char smem[];
    const u32 sb = smem_u32(smem);
    int* nextp = (int*)(smem + 131072);

    const int tid = threadIdx.x;
    const int wid = tid >> 5;
    const int l   = tid & 31;
    const int R0  = (wid >> 3) * 32;     // 0 or 32
    const int N0  = (wid & 7) * 16;      // 0..112

    // ldmatrix lane address components
    const int ar = (l & 15);
    const int ac = (l >> 4);
    const int br = (l & 7) + ((l >> 4) & 1) * 8;
    const int bc = (l >> 3) & 1;

    // Prologue: W hi/lo via cp.async (2048 16B chunks each, 4/thread)
    #pragma unroll
    for (int i = 0; i < 4; ++i) {
        u32 d = sb + (u32)(tid + i * 512) * 16u;
        CP_ASYNC16(d,         (const char*)Whi + (tid + i * 512) * 16);
        CP_ASYNC16(d + 32768, (const char*)Wlo + (tid + i * 512) * 16);
    }

    // Bias pairs per lane (fp32 out path)
    float2 bv[2];
    bv[0] = make_float2(0.f, 0.f); bv[1] = make_float2(0.f, 0.f);
    if (!HALF_OUT && bias) {
        bv[0] = *(const float2*)(bias + N0 + 0 + 2 * (l & 3));
        bv[1] = *(const float2*)(bias + N0 + 8 + 2 * (l & 3));
    }

    float4 pre[4];                       // convert-mode register prefetch

    int t_cur = blockIdx.x;

    // First A tile
    if (t_cur < ntiles) {
        if (LOAD_SPLIT) {
            u32 dst = sb + 65536;
            const char* shp = (const char*)Ahi_g + (size_t)t_cur * 16384;
            const char* slp = (const char*)Alo_g + (size_t)t_cur * 16384;
            #pragma unroll
            for (int i = 0; i < 2; ++i) {
                CP_ASYNC16(dst + (u32)(tid + i * 512) * 16u, shp + (tid + i * 512) * 16);
                CP_ASYNC16(dst + 16384 + (u32)(tid + i * 512) * 16u, slp + (tid + i * 512) * 16);
            }
        } else {
            #pragma unroll
            for (int i = 0; i < 4; ++i) {
                int e4 = tid + i * 512;
                int row = t_cur * 64 + (e4 >> 5);
                pre[i] = make_float4(0.f, 0.f, 0.f, 0.f);
                if (row < n) pre[i] = *(const float4*)(Af32 + (size_t)row * DD + (e4 & 31) * 4);
            }
        }
    }
    CP_COMMIT();
    if (tid == 0) nextp[0] = atomicAdd(&g_tctr[slot], 1);
    CP_WAIT0();
    if (!LOAD_SPLIT && t_cur < ntiles) {
        // convert prefetched A into buf0
        char* dst = smem + 65536;
        #pragma unroll
        for (int i = 0; i < 4; ++i) {
            int e4 = tid + i * 512;
            int r = e4 >> 5, c4 = e4 & 31;
            float f[4] = {pre[i].x, pre[i].y, pre[i].z, pre[i].w};
            unsigned short hs[4], ls[4];
            #pragma unroll
            for (int j = 0; j < 4; ++j) split_bf16(f[j], hs[j], ls[j]);
            u32 off = tile_off(r, c4 >> 1) + (u32)(c4 & 1) * 8u;
            *(ushort4*)(dst + off)         = make_ushort4(hs[0], hs[1], hs[2], hs[3]);
            *(ushort4*)(dst + 16384 + off) = make_ushort4(ls[0], ls[1], ls[2], ls[3]);
        }
    }
    __syncthreads();
    int parity = 0, cur = 0;
    int t_next = nextp[0];

    while (t_cur < ntiles) {
        // Kick off next tile load into buf[cur^1]
        if (t_next < ntiles) {
            if (LOAD_SPLIT) {
                u32 dst = sb + 65536 + (u32)(cur ^ 1) * 32768u;
                const char* shp = (const char*)Ahi_g + (size_t)t_next * 16384;
                const char* slp = (const char*)Alo_g + (size_t)t_next * 16384;
                #pragma unroll
                for (int i = 0; i < 2; ++i) {
                    CP_ASYNC16(dst + (u32)(tid + i * 512) * 16u, shp + (tid + i * 512) * 16);
                    CP_ASYNC16(dst + 16384 + (u32)(tid + i * 512) * 16u, slp + (tid + i * 512) * 16);
                }
                CP_COMMIT();
            } else {
                #pragma unroll
                for (int i = 0; i < 4; ++i) {
                    int e4 = tid + i * 512;
                    int row = t_next * 64 + (e4 >> 5);
                    pre[i] = make_float4(0.f, 0.f, 0.f, 0.f);
                    if (row < n) pre[i] = *(const float4*)(Af32 + (size_t)row * DD + (e4 & 31) * 4);
                }
            }
        }
        if (tid == 0) nextp[parity ^ 1] = atomicAdd(&g_tctr[slot], 1);

        // ---- MMA on buf[cur] ----
        const u32 aAh = sb + 65536 + (u32)cur * 32768u;
        const u32 aAl = aAh + 16384;

        float acc[2][2][4];
        #pragma unroll
        for (int mt = 0; mt < 2; ++mt)
            #pragma unroll
            for (int nb = 0; nb < 2; ++nb)
                #pragma unroll
                for (int q = 0; q < 4; ++q) acc[mt][nb][q] = 0.f;

        #pragma unroll
        for (int kk = 0; kk < 8; ++kk) {
            u32 ah[2][4], al[2][4], bh[4], bl[4];
            #pragma unroll
            for (int mt = 0; mt < 2; ++mt) {
                u32 off = tile_off(R0 + mt * 16 + ar, 2 * kk + ac);
                ldm_x4(ah[mt], aAh + off);
                ldm_x4(al[mt], aAl + off);
            }
            u32 boff = tile_off(N0 + br, 2 * kk + bc);
            ldm_x4(bh, sb + boff);
            ldm_x4(bl, sb + 32768 + boff);
            #pragma unroll
            for (int mt = 0; mt < 2; ++mt) {
                mma16816(acc[mt][0], ah[mt], bh + 0);
                mma16816(acc[mt][0], ah[mt], bl + 0);
                mma16816(acc[mt][0], al[mt], bh + 0);
                mma16816(acc[mt][1], ah[mt], bh + 2);
                mma16816(acc[mt][1], ah[mt], bl + 2);
                mma16816(acc[mt][1], al[mt], bh + 2);
            }
        }

        // Convert-mode: store prefetched next tile into buf[cur^1]
        if (!LOAD_SPLIT && t_next < ntiles) {
            char* dst = smem + 65536 + (cur ^ 1) * 32768;
            #pragma unroll
            for (int i = 0; i < 4; ++i) {
                int e4 = tid + i * 512;
                int r = e4 >> 5, c4 = e4 & 31;
                float f[4] = {pre[i].x, pre[i].y, pre[i].z, pre[i].w};
                unsigned short hs[4], ls[4];
                #pragma unroll
                for (int j = 0; j < 4; ++j) split_bf16(f[j], hs[j], ls[j]);
                u32 off = tile_off(r, c4 >> 1) + (u32)(c4 & 1) * 8u;
                *(ushort4*)(dst + off)         = make_ushort4(hs[0], hs[1], hs[2], hs[3]);
                *(ushort4*)(dst + 16384 + off) = make_ushort4(ls[0], ls[1], ls[2], ls[3]);
            }
        }

        // ---- Epilogue for t_cur ----
        #pragma unroll
        for (int mt = 0; mt < 2; ++mt) {
            int rows[2];
            rows[0] = t_cur * 64 + R0 + mt * 16 + (l >> 2);
            rows[1] = rows[0] + 8;
            #pragma unroll
            for (int nb = 0; nb < 2; ++nb) {
                int col = N0 + nb * 8 + 2 * (l & 3);
                const float* d = acc[mt][nb];
                #pragma unroll
                for (int h2 = 0; h2 < 2; ++h2) {
                    int row = rows[h2];
                    if (row >= n) continue;
                    float v0 = d[2 * h2 + 0], v1 = d[2 * h2 + 1];
                    if (HALF_OUT) {
                        *(__half2*)((__half*)Cv + (size_t)row * DD + col) =
                            __floats2half2_rn(v0, v1);
                    } else {
                        v0 += bv[nb].x; v1 += bv[nb].y;
                        *(float2*)((float*)Cv + (size_t)row * DD + col) = make_float2(v0, v1);
                        if (SPLIT_OUT) {
                            unsigned short h0, l0, h1, l1;
                            split_bf16(v0, h0, l0);
                            split_bf16(v1, h1, l1);
                            size_t o = (size_t)(row >> 6) * 16384 +
                                       tile_off(row & 63, col >> 3) + (col & 7) * 2;
                            *(u32*)((char*)Ohi + o) = (u32)h0 | ((u32)h1 << 16);
                            *(u32*)((char*)Olo + o) = (u32)l0 | ((u32)l1 << 16);
                        }
                    }
                }
            }
        }

        CP_WAIT0();
        __syncthreads();
        t_cur = t_next;
        t_next = nextp[parity ^ 1];
        parity ^= 1;
        cur ^= 1;
    }
}

// ---------------------------------------------------------------------------
// Detect int64 vs int32 edge_index: one warp, 128 values, ballot.
// ---------------------------------------------------------------------------
__global__ void detect_idx_kernel(const long long* __restrict__ p) {
    int t = threadIdx.x;
    int bad = 0;
    #pragma unroll
    for (int i = 0; i < 4; ++i) {
        long long v = p[t + i * 32];
        bad |= (v < 0 || v >= NN);
    }
    unsigned m = __ballot_sync(0xffffffffu, bad);
    if (t == 0) g_is64 = (m == 0);
}

__device__ __forceinline__ int load_idx(const void* p, int i) {
    return g_is64 ? (int)((const long long*)p)[i] : ((const int*)p)[i];
}

// ---------------------------------------------------------------------------
// CSR construction: zero -> histogram -> 3-phase scan -> fill
// ---------------------------------------------------------------------------
__global__ void zero_deg_kernel(int* __restrict__ deg, int n) {
    int i = blockIdx.x * blockDim.x + threadIdx.x;
    if (i < n) deg[i] = 0;
}

__global__ void hist_kernel(const void* __restrict__ eidx, int* __restrict__ deg, int E) {
    int e = blockIdx.x * blockDim.x + threadIdx.x;
    if (e >= E) return;
    atomicAdd(&deg[load_idx(eidx, e)], 1);
}

__global__ void scan_phase1(const int* __restrict__ deg, int* __restrict__ rowptr,
                            int* __restrict__ partial, int n) {
    __shared__ int sm[SCAN_BLK];
    const int t = threadIdx.x;
    const int i = blockIdx.x * SCAN_BLK + t;
    int v = (i < n) ? deg[i] : 0;
    sm[t] = v;
    __syncthreads();
    #pragma unroll
    for (int off = 1; off < SCAN_BLK; off <<= 1) {
        int u = (t >= off) ? sm[t - off] : 0;
        __syncthreads();
        sm[t] += u;
        __syncthreads();
    }
    if (i < n) rowptr[i] = sm[t] - v;
    if (t == SCAN_BLK - 1) partial[blockIdx.x] = sm[t];
}

__global__ void scan_phase2(int* __restrict__ partial, int nb,
                            int* __restrict__ rowptr, int n, int E) {
    __shared__ int sm[1024];
    const int t = threadIdx.x;
    int v = (t < nb) ? partial[t] : 0;
    sm[t] = v;
    __syncthreads();
    #pragma unroll
    for (int off = 1; off < 1024; off <<= 1) {
        int u = (t >= off) ? sm[t - off] : 0;
        __syncthreads();
        sm[t] += u;
        __syncthreads();
    }
    if (t < nb) partial[t] = sm[t] - v;
    if (t == 0) rowptr[n] = E;
}

__global__ void scan_phase3(int* __restrict__ rowptr, int* __restrict__ ctr,
                            const int* __restrict__ partial, int n) {
    int i = blockIdx.x * SCAN_BLK + threadIdx.x;
    if (i < n) {
        int v = rowptr[i] + partial[blockIdx.x];
        rowptr[i] = v;
        ctr[i] = v;
    }
}

__global__ void fill_kernel(const void* __restrict__ eidx, int* __restrict__ ctr,
                            int* __restrict__ csrcol, int E) {
    int e = blockIdx.x * blockDim.x + threadIdx.x;
    if (e >= E) return;
    int row = load_idx(eidx, e);
    int col = load_idx(eidx, E + e);
    int pos = atomicAdd(&ctr[row], 1);
    csrcol[pos] = col;
}

// ---------------------------------------------------------------------------
// Fused gather-aggregate + relu + residual: one warp per node, z in fp16.
// SPLIT_OUT=1 additionally writes the updated h as split-bf16 tiles.
// ---------------------------------------------------------------------------
template <int SPLIT_OUT>
__global__ __launch_bounds__(256)
void gather_relu_res_kernel(const int* __restrict__ rowptr,
                            const int* __restrict__ csrcol,
                            const __half* __restrict__ z,
                            float* __restrict__ h,
                            const float* __restrict__ b,
                            __nv_bfloat16* __restrict__ Ohi,
                            __nv_bfloat16* __restrict__ Olo, int n) {
    int warp = (blockIdx.x * blockDim.x + threadIdx.x) >> 5;
    int lane = threadIdx.x & 31;
    if (warp >= n) return;

    const int s = rowptr[warp];
    const int e = rowptr[warp + 1];
    const int off = lane * 4;

    float4 acc = make_float4(0.f, 0.f, 0.f, 0.f);

    int j = s;
    for (; j + 4 <= e; j += 4) {
        int c0 = csrcol[j + 0];
        int c1 = csrcol[j + 1];
        int c2 = csrcol[j + 2];
        int c3 = csrcol[j + 3];
        __half2 p0[2], p1[2], p2[2], p3[2];
        *reinterpret_cast<uint2*>(p0) = *reinterpret_cast<const uint2*>(z + (size_t)c0 * DD + off);
        *reinterpret_cast<uint2*>(p1) = *reinterpret_cast<const uint2*>(z + (size_t)c1 * DD + off);
        *reinterpret_cast<uint2*>(p2) = *reinterpret_cast<const uint2*>(z + (size_t)c2 * DD + off);
        *reinterpret_cast<uint2*>(p3) = *reinterpret_cast<const uint2*>(z + (size_t)c3 * DD + off);
        float2 f;
        f = __half22float2(p0[0]); acc.x += f.x; acc.y += f.y;
        f = __half22float2(p0[1]); acc.z += f.x; acc.w += f.y;
        f = __half22float2(p1[0]); acc.x += f.x; acc.y += f.y;
        f = __half22float2(p1[1]); acc.z += f.x; acc.w += f.y;
        f = __half22float2(p2[0]); acc.x += f.x; acc.y += f.y;
        f = __half22float2(p2[1]); acc.z += f.x; acc.w += f.y;
        f = __half22float2(p3[0]); acc.x += f.x; acc.y += f.y;
        f = __half22float2(p3[1]); acc.z += f.x; acc.w += f.y;
    }
    for (; j < e; ++j) {
        int c = csrcol[j];
        __half2 p[2];
        *reinterpret_cast<uint2*>(p) = *reinterpret_cast<const uint2*>(z + (size_t)c * DD + off);
        float2 f;
        f = __half22float2(p[0]); acc.x += f.x; acc.y += f.y;
        f = __half22float2(p[1]); acc.z += f.x; acc.w += f.y;
    }

    float4 bvv = *reinterpret_cast<const float4*>(b + off);
    float4 hv = *reinterpret_cast<float4*>(h + (size_t)warp * DD + off);
    hv.x += fmaxf(acc.x + bvv.x, 0.f);
    hv.y += fmaxf(acc.y + bvv.y, 0.f);
    hv.z += fmaxf(acc.z + bvv.z, 0.f);
    hv.w += fmaxf(acc.w + bvv.w, 0.f);
    *reinterpret_cast<float4*>(h + (size_t)warp * DD + off) = hv;

    if (SPLIT_OUT) {
        float v[4] = {hv.x, hv.y, hv.z, hv.w};
        unsigned short hs[4], ls[4];
        #pragma unroll
        for (int q = 0; q < 4; ++q) split_bf16(v[q], hs[q], ls[q]);
        size_t o = (size_t)(warp >> 6) * 16384 +
                   tile_off(warp & 63, off >> 3) + (off & 7) * 2;
        *(ushort4*)((char*)Ohi + o) = make_ushort4(hs[0], hs[1], hs[2], hs[3]);
        *(ushort4*)((char*)Olo + o) = make_ushort4(ls[0], ls[1], ls[2], ls[3]);
    }
}

// ---------------------------------------------------------------------------
extern "C" void kernel_launch(void* const* d_in, const int* in_sizes, int n_in,
                              void* d_out, int out_size) {
    const float* x   = (const float*)d_in[0];
    const void*  eix = d_in[1];
    const float* W_t = (const float*)d_in[2];
    const float* b_t = (const float*)d_in[3];
    const float* W0  = (const float*)d_in[4];
    const float* b0  = (const float*)d_in[5];
    const float* W1  = (const float*)d_in[6];
    const float* b1  = (const float*)d_in[7];
    float* h = (float*)d_out;

    const int n = in_sizes[0] / DD;   // 40000
    const int E = in_sizes[1] / 2;    // 640000

    __half* z_ptr;
    int *deg_ptr, *rowptr_ptr, *ctr_ptr, *csrcol_ptr, *partial_ptr;
    __nv_bfloat16 *whi, *wlo, *ahi, *alo;
    cudaGetSymbolAddress((void**)&z_ptr, g_z);
    cudaGetSymbolAddress((void**)&deg_ptr, g_deg);
    cudaGetSymbolAddress((void**)&rowptr_ptr, g_rowptr);
    cudaGetSymbolAddress((void**)&ctr_ptr, g_ctr);
    cudaGetSymbolAddress((void**)&csrcol_ptr, g_csrcol);
    cudaGetSymbolAddress((void**)&partial_ptr, g_partial);
    cudaGetSymbolAddress((void**)&whi, g_Whi);
    cudaGetSymbolAddress((void**)&wlo, g_Wlo);
    cudaGetSymbolAddress((void**)&ahi, g_Ahi);
    cudaGetSymbolAddress((void**)&alo, g_Alo);

    cudaFuncSetAttribute(tgemm_kernel<0, 0, 1>,
                         cudaFuncAttributeMaxDynamicSharedMemorySize, GEMM_SMEM);
    cudaFuncSetAttribute(tgemm_kernel<1, 1, 0>,
                         cudaFuncAttributeMaxDynamicSharedMemorySize, GEMM_SMEM);

    const int ntiles = (n + 63) / 64;               // 625
    const int ggrid  = ntiles < PGRID ? ntiles : PGRID;
    const int edge_blocks = (E + 255) / 256;
    const int node_blocks = (n * 32 + 255) / 256;   // warp per node
    const int scan_blocks = (n + SCAN_BLK - 1) / SCAN_BLK;

    // Side stream (host objects only; replays execute the captured graph).
    cudaStream_t side;
    cudaStreamCreateWithFlags(&side, cudaStreamNonBlocking);
    cudaEvent_t evF, evW0, evJ, evW1;
    cudaEventCreateWithFlags(&evF, cudaEventDisableTiming);
    cudaEventCreateWithFlags(&evW0, cudaEventDisableTiming);
    cudaEventCreateWithFlags(&evJ, cudaEventDisableTiming);
    cudaEventCreateWithFlags(&evW1, cudaEventDisableTiming);

    cudaEventRecord(evF, 0);
    cudaStreamWaitEvent(side, evF, 0);

    // MAIN: W_t conversion (+ counter reset) directly, then GEMM_t — no
    // cross-stream wait on the critical path.
    wconv_kernel<<<64, 256>>>(W_t, whi, wlo, 1, ggrid);              // 0 main
    // SIDE: W0 first (needed by GEMM_0 soon), then CSR build, then W1.
    wconv_kernel<<<64, 256, 0, side>>>(W0, whi + 16384, wlo + 16384, 0, 0);
    cudaEventRecord(evW0, side);
    tgemm_kernel<0, 0, 1><<<ggrid, THREADS_G, GEMM_SMEM>>>(
        x, nullptr, nullptr, whi, wlo, b_t, h, ahi, alo, n, ntiles, 0);  // main
    detect_idx_kernel<<<1, 32, 0, side>>>((const long long*)eix);
    zero_deg_kernel<<<(n + 255) / 256, 256, 0, side>>>(deg_ptr, n);
    hist_kernel<<<edge_blocks, 256, 0, side>>>(eix, deg_ptr, E);
    scan_phase1<<<scan_blocks, SCAN_BLK, 0, side>>>(deg_ptr, rowptr_ptr, partial_ptr, n);
    scan_phase2<<<1, 1024, 0, side>>>(partial_ptr, scan_blocks, rowptr_ptr, n, E);
    scan_phase3<<<scan_blocks, SCAN_BLK, 0, side>>>(rowptr_ptr, ctr_ptr, partial_ptr, n);
    fill_kernel<<<edge_blocks, 256, 0, side>>>(eix, ctr_ptr, csrcol_ptr, E);
    cudaEventRecord(evJ, side);
    wconv_kernel<<<64, 256, 0, side>>>(W1, whi + 2 * 16384, wlo + 2 * 16384, 0, 0);
    cudaEventRecord(evW1, side);

    // z = h @ W0 (fp16 out), A from split tiles
    cudaStreamWaitEvent(0, evW0, 0);
    tgemm_kernel<1, 1, 0><<<ggrid, THREADS_G, GEMM_SMEM>>>(
        nullptr, ahi, alo, whi + 16384, wlo + 16384, nullptr, z_ptr,
        nullptr, nullptr, n, ntiles, 1);

    // join: gathers need the CSR
    cudaStreamWaitEvent(0, evJ, 0);

    // layer 0: h += relu(gather(z) + b0); also refresh split-bf16 h tiles
    gather_relu_res_kernel<1><<<node_blocks, 256>>>(
        rowptr_ptr, csrcol_ptr, z_ptr, h, b0, ahi, alo, n);

    // layer 1
    cudaStreamWaitEvent(0, evW1, 0);
    tgemm_kernel<1, 1, 0><<<ggrid, THREADS_G, GEMM_SMEM>>>(
        nullptr, ahi, alo, whi + 2 * 16384, wlo + 2 * 16384, nullptr, z_ptr,
        nullptr, nullptr, n, ntiles, 2);
    gather_relu_res_kernel<0><<<node_blocks, 256>>>(
        rowptr_ptr, csrcol_ptr, z_ptr, h, b1, nullptr, nullptr, n);
}